// round 11
// baseline (speedup 1.0000x reference)
#include <cuda_runtime.h>
#include <cuda_fp16.h>
#include <cstdint>
#include <cfloat>

#define N_EMB   8192
#define DDIM    256
#define BB      32
#define HW      1024
#define NQ      32768
#define ZQ_ELEMS 8388608
#define SPLITS  8
#define KSPL    1024
#define QT      128
#define CCH     256
#define GCH     256
#define NST     32
#define TAU     0.20f

#define SM_A    0               // 128 q x 256 k halves, swizzled = 65536 B
#define SM_B    65536           // 2 stages x 16384 B (256 codes x 32 k halves)
#define SM_EH   98304           // 1024 floats
#define SM_RED  102400          // rv1/ri1/rv2 3 x 2048 B
#define SMEM_ALLOC 108544

__device__ float  g_ehn[N_EMB];
__device__ __half g_eh[N_EMB * DDIM];
__device__ float  g_p1v[SPLITS * NQ];
__device__ int    g_p1i[SPLITS * NQ];
__device__ float  g_p2v[SPLITS * NQ];
__device__ float  g_cmin[GCH * NQ];
__device__ float  g_b1[NQ];
__device__ int    g_idx[NQ];
__device__ int    g_flag[NQ];
__device__ int    g_nflag;
__device__ double g_diff;

__device__ __forceinline__ uint32_t smem_u32(const void* p) {
    uint32_t a;
    asm("{ .reg .u64 t; cvta.to.shared.u64 t, %1; cvt.u32.u64 %0, t; }"
        : "=r"(a) : "l"(p));
    return a;
}
__device__ __forceinline__ void cp16(uint32_t s, const void* g) {
    asm volatile("cp.async.cg.shared.global [%0], [%1], 16;"
                 :: "r"(s), "l"(g) : "memory");
}
#define CP_COMMIT() asm volatile("cp.async.commit_group;" ::: "memory")
#define CP_WAIT0()  asm volatile("cp.async.wait_group 0;" ::: "memory")

#define LDMX4(r0, r1, r2, r3, addr) \
    asm volatile("ldmatrix.sync.aligned.m8n8.x4.shared.b16 {%0,%1,%2,%3},[%4];" \
        : "=r"(r0), "=r"(r1), "=r"(r2), "=r"(r3) : "r"(addr))
#define MMA_F16(d, a, b0, b1) \
    asm volatile("mma.sync.aligned.m16n8k16.row.col.f32.f16.f16.f32 " \
        "{%0,%1,%2,%3},{%4,%5,%6,%7},{%8,%9},{%0,%1,%2,%3};" \
        : "+f"((d)[0]), "+f"((d)[1]), "+f"((d)[2]), "+f"((d)[3]) \
        : "r"((a)[0]), "r"((a)[1]), "r"((a)[2]), "r"((a)[3]), "r"(b0), "r"(b1))

__global__ void k_prep(const float* __restrict__ emb) {
    if (blockIdx.x == 0 && threadIdx.x == 0) { g_diff = 0.0; g_nflag = 0; }
    int row  = blockIdx.x * 8 + (threadIdx.x >> 5);
    int lane = threadIdx.x & 31;
    const float4* e4 = (const float4*)(emb + (size_t)row * DDIM);
    __half2* eh2 = (__half2*)(g_eh + (size_t)row * DDIM);
    float s = 0.f;
    for (int i = lane; i < DDIM / 4; i += 32) {
        float4 v = e4[i];
        s += v.x * v.x + v.y * v.y + v.z * v.z + v.w * v.w;
        eh2[2 * i]     = __floats2half2_rn(v.x, v.y);
        eh2[2 * i + 1] = __floats2half2_rn(v.z, v.w);
    }
#pragma unroll
    for (int o = 16; o; o >>= 1) s += __shfl_xor_sync(0xffffffffu, s, o);
    if (lane == 0) g_ehn[row] = 0.5f * s;
}

// grid (256, 8), block 256 (8 warps: 2M x 4N, warp tile 64x64), 1 CTA/SM
__global__ void __launch_bounds__(256, 1)
k_gemm(const float* __restrict__ z) {
    extern __shared__ char sm[];
    const uint32_t smA = smem_u32(sm);
    float* ehs = (float*)(sm + SM_EH);
    float* rv1 = (float*)(sm + SM_RED);
    int*   ri1 = (int*)(sm + SM_RED + 2048);
    float* rv2 = (float*)(sm + SM_RED + 4096);

    const int tid = threadIdx.x, wid = tid >> 5, lane = tid & 31;
    const int warpM = wid >> 2, warpN = wid & 3;
    const int g = lane >> 2, t = lane & 3;
    const int qbase = blockIdx.x * QT, sp = blockIdx.y;
    const int bb = qbase / HW, nb = qbase % HW;
    const int kbase = sp * KSPL;

    for (int i = tid; i < KSPL; i += 256) ehs[i] = g_ehn[kbase + i];

    // A staging: z[128 q][256 k] -> half, swizzled [q][kblk^q]
    const float* zb = z + (size_t)bb * DDIM * HW + nb;
    for (int i = tid; i < QT * DDIM; i += 256) {
        int q = i & 127, k = i >> 7;
        __half hv = __float2half_rn(zb[(size_t)k * HW + q]);
        int kblk = k >> 3;
        uint32_t off = q * 512 + (((kblk & 24) | ((kblk ^ q) & 7)) << 4)
                     + (k & 7) * 2;
        *(__half*)(sm + off) = hv;
    }

    // B stage: 256 codes x 32 k halves (64B rows), XOR-swizzled 16B chunks
    auto prefetch = [&](int s) {
        int cc = s >> 3, kb = s & 7, buf = s & 1;
        const __half* src = g_eh + (size_t)(kbase + cc * CCH) * DDIM + kb * 32;
        uint32_t dst = smA + 65536 + buf * 16384;
#pragma unroll
        for (int it = 0; it < 4; it++) {
            int idx = it * 256 + tid;
            int code = idx >> 2, kblk = idx & 3;
            cp16(dst + code * 64 + (((kblk ^ ((code >> 1) & 3))) << 4),
                 src + (size_t)code * DDIM + kblk * 8);
        }
    };

    float D[4][8][4];
    float bv1[4][2], bv2[4][2];
    int   bix[4][2];
#pragma unroll
    for (int a = 0; a < 4; a++)
#pragma unroll
        for (int h = 0; h < 2; h++) {
            bv1[a][h] = FLT_MAX; bv2[a][h] = FLT_MAX; bix[a][h] = 0;
        }

    prefetch(0);
    CP_COMMIT();
    const int r_ld = (lane & 7) | (lane & 8);   // A frag row
    const int cbhi = (lane >> 4) & 1;           // A col halfblock
    // B LDMX4 lane addressing: quad = lane>>3 -> {nt even k0, nt even k1,
    //                                             nt odd k0,  nt odd k1}
    const int bquad = lane >> 3, brow8 = lane & 7;

    for (int s = 0; s < NST; s++) {
        CP_WAIT0();
        __syncthreads();          // buf s ready AND all warps done with s-1
        if (s + 1 < NST) { prefetch(s + 1); CP_COMMIT(); }
        if ((s & 7) == 0) {
#pragma unroll
            for (int mt = 0; mt < 4; mt++)
#pragma unroll
                for (int nt = 0; nt < 8; nt++)
#pragma unroll
                    for (int c = 0; c < 4; c++) D[mt][nt][c] = 0.f;
        }
        const uint32_t bst = smA + 65536 + (s & 1) * 16384;
        const int kb = s & 7;
#pragma unroll
        for (int ks = 0; ks < 2; ks++) {
            const int kk = kb * 2 + ks;                 // kstep in chunk 0..15
            const int cb = kk * 2 + cbhi;               // A 16B col block 0..31
            uint32_t a[4][4];
#pragma unroll
            for (int mt = 0; mt < 4; mt++) {
                int mrow = warpM * 64 + mt * 16 + r_ld;
                uint32_t ad = smA + mrow * 512
                            + (((cb & 24) | ((cb ^ mrow) & 7)) << 4);
                LDMX4(a[mt][0], a[mt][1], a[mt][2], a[mt][3], ad);
            }
#pragma unroll
            for (int np = 0; np < 4; np++) {
                int code = warpN * 64 + np * 16 + ((bquad >> 1) * 8) + brow8;
                int kblk = ks * 2 + (bquad & 1);
                uint32_t bad = bst + code * 64
                             + (((kblk ^ ((code >> 1) & 3))) << 4);
                uint32_t b0, b1, b2, b3;
                LDMX4(b0, b1, b2, b3, bad);
#pragma unroll
                for (int mt = 0; mt < 4; mt++) {
                    MMA_F16(D[mt][2 * np],     a[mt], b0, b1);
                    MMA_F16(D[mt][2 * np + 1], a[mt], b2, b3);
                }
            }
        }
        if ((s & 7) == 7) {
            const int cc = s >> 3;
            float eh[8][2];
#pragma unroll
            for (int nt = 0; nt < 8; nt++) {
                int cl = cc * CCH + warpN * 64 + nt * 8 + 2 * t;
                eh[nt][0] = ehs[cl]; eh[nt][1] = ehs[cl + 1];
            }
#pragma unroll
            for (int mt = 0; mt < 4; mt++)
#pragma unroll
                for (int h = 0; h < 2; h++) {
                    float cm0 = FLT_MAX, cm1 = FLT_MAX;
#pragma unroll
                    for (int nt = 0; nt < 8; nt++)
#pragma unroll
                        for (int c = 0; c < 2; c++) {
                            float v = eh[nt][c] - D[mt][nt][h * 2 + c];
                            int gi = kbase + cc * CCH + warpN * 64 + nt * 8
                                   + 2 * t + c;
                            if (nt < 4) cm0 = fminf(cm0, v);
                            else        cm1 = fminf(cm1, v);
                            if (v < bv1[mt][h] ||
                                (v == bv1[mt][h] && gi < bix[mt][h])) {
                                bv2[mt][h] = bv1[mt][h];
                                bv1[mt][h] = v; bix[mt][h] = gi;
                            } else {
                                bv2[mt][h] = fminf(bv2[mt][h], v);
                            }
                        }
                    cm0 = fminf(cm0, __shfl_xor_sync(0xffffffffu, cm0, 1));
                    cm0 = fminf(cm0, __shfl_xor_sync(0xffffffffu, cm0, 2));
                    cm1 = fminf(cm1, __shfl_xor_sync(0xffffffffu, cm1, 1));
                    cm1 = fminf(cm1, __shfl_xor_sync(0xffffffffu, cm1, 2));
                    if (t == 0) {
                        int row = warpM * 64 + mt * 16 + h * 8 + g;
                        int sl0 = sp * 32 + cc * 8 + warpN * 2;
                        g_cmin[(size_t)sl0 * NQ + qbase + row] = cm0;
                        g_cmin[(size_t)(sl0 + 1) * NQ + qbase + row] = cm1;
                    }
                }
        }
    }
    __syncthreads();

#pragma unroll
    for (int mt = 0; mt < 4; mt++)
#pragma unroll
        for (int h = 0; h < 2; h++) {
            float v1 = bv1[mt][h], v2 = bv2[mt][h];
            int i1 = bix[mt][h];
#pragma unroll
            for (int o = 1; o <= 2; o <<= 1) {
                float pv1 = __shfl_xor_sync(0xffffffffu, v1, o);
                float pv2 = __shfl_xor_sync(0xffffffffu, v2, o);
                int   pi1 = __shfl_xor_sync(0xffffffffu, i1, o);
                if (pv1 < v1 || (pv1 == v1 && pi1 < i1)) {
                    v2 = fminf(v1, pv2); v1 = pv1; i1 = pi1;
                } else {
                    v2 = fminf(pv1, v2);
                }
            }
            if (t == 0) {
                int row = warpM * 64 + mt * 16 + h * 8 + g;
                rv1[row * 4 + warpN] = v1;
                ri1[row * 4 + warpN] = i1;
                rv2[row * 4 + warpN] = v2;
            }
        }
    __syncthreads();
    if (tid < 128) {
        float v1 = rv1[tid * 4]; int i1 = ri1[tid * 4]; float v2 = rv2[tid * 4];
#pragma unroll
        for (int wn = 1; wn < 4; wn++) {
            float pv1 = rv1[tid * 4 + wn], pv2 = rv2[tid * 4 + wn];
            int   pi1 = ri1[tid * 4 + wn];
            if (pv1 < v1 || (pv1 == v1 && pi1 < i1)) {
                v2 = fminf(v1, pv2); v1 = pv1; i1 = pi1;
            } else {
                v2 = fminf(pv1, v2);
            }
        }
        g_p1v[sp * NQ + qbase + tid] = v1;
        g_p1i[sp * NQ + qbase + tid] = i1;
        g_p2v[sp * NQ + qbase + tid] = v2;
    }
}

__global__ void k_reduce() {
    int q = blockIdx.x * 256 + threadIdx.x;
    float b1 = FLT_MAX, b2 = FLT_MAX;
    int i1 = 0;
#pragma unroll
    for (int s = 0; s < SPLITS; s++) {
        float v1 = g_p1v[s * NQ + q];
        int   ii = g_p1i[s * NQ + q];
        float v2 = g_p2v[s * NQ + q];
        if (v1 < b1) { b2 = b1; b1 = v1; i1 = ii; }
        else if (v1 < b2) b2 = v1;
        if (v2 < b2) b2 = v2;
    }
    g_idx[q] = i1;
    g_b1[q]  = b1;
    if (b2 - b1 <= TAU) {
        int p = atomicAdd(&g_nflag, 1);
        g_flag[p] = q;
    }
}

__global__ void __launch_bounds__(256, 2)
k_refine(const float* __restrict__ z, const float* __restrict__ emb) {
    __shared__ float zs[DDIM];
    __shared__ short clist[GCH];
    __shared__ int   ncand;
    __shared__ float wv[8];
    __shared__ int   wi[8];
    const int tid = threadIdx.x, wid = tid >> 5, lane = tid & 31;
    const int grp = lane >> 3, gl = lane & 7;
    const int nf = g_nflag;
    for (int fi = blockIdx.x; fi < nf; fi += gridDim.x) {
        const int q = g_flag[fi];
        if (tid == 0) ncand = 0;
        __syncthreads();
        zs[tid] = z[((size_t)(q >> 10) * DDIM + tid) * HW + (q & (HW - 1))];
        __syncthreads();
        float4 zr[8];
#pragma unroll
        for (int j = 0; j < 8; j++) zr[j] = *(const float4*)(zs + gl * 32 + j * 4);
        const float thr = g_b1[q] + TAU;
        if (tid < GCH && g_cmin[(size_t)tid * NQ + q] <= thr) {
            int p = atomicAdd(&ncand, 1);
            clist[p] = (short)tid;
        }
        __syncthreads();
        const int nc = ncand;
        float bv = FLT_MAX;
        int   bi = 0x7fffffff;
        for (int ci = 0; ci < nc; ci++) {
            const int code = clist[ci] * 32 + wid * 4 + grp;
            const float4* er = (const float4*)(emb + (size_t)code * DDIM + gl * 32);
            float s = 0.f;
#pragma unroll
            for (int j = 0; j < 8; j++) {
                float4 e = er[j];
                s += e.x * zr[j].x + e.y * zr[j].y + e.z * zr[j].z + e.w * zr[j].w;
            }
            s += __shfl_xor_sync(0xffffffffu, s, 1);
            s += __shfl_xor_sync(0xffffffffu, s, 2);
            s += __shfl_xor_sync(0xffffffffu, s, 4);
            float v = g_ehn[code] - s;
            if (v < bv || (v == bv && code < bi)) { bv = v; bi = code; }
        }
#pragma unroll
        for (int o = 8; o <= 16; o <<= 1) {
            float pv = __shfl_xor_sync(0xffffffffu, bv, o);
            int   pi = __shfl_xor_sync(0xffffffffu, bi, o);
            if (pv < bv || (pv == bv && pi < bi)) { bv = pv; bi = pi; }
        }
        if (lane == 0) { wv[wid] = bv; wi[wid] = bi; }
        __syncthreads();
        if (tid == 0) {
            float fv = wv[0]; int fx = wi[0];
#pragma unroll
            for (int w2 = 1; w2 < 8; w2++)
                if (wv[w2] < fv || (wv[w2] == fv && wi[w2] < fx)) {
                    fv = wv[w2]; fx = wi[w2];
                }
            g_idx[q] = fx;
        }
        __syncthreads();
    }
}

__global__ void k_scatter(const float* __restrict__ z,
                          const float* __restrict__ emb,
                          float* __restrict__ out) {
    __shared__ float Ts[32][257];
    __shared__ int   sidx[32];
    __shared__ float spart[8];
    const int bh = blockIdx.x;
    const int b  = bh >> 5;
    const int h  = bh & 31;
    const int t  = threadIdx.x;

    if (t < 32) {
        int ix = g_idx[b * HW + h * 32 + t];
        sidx[t] = ix;
        out[ZQ_ELEMS + 1 + b * HW + h * 32 + t] = (float)ix;
    }
    __syncthreads();
    {
        const int wr = t >> 3;
        const int c0 = (t & 7) * 32;
        const float* er = emb + (size_t)sidx[wr] * DDIM + c0;
        for (int c = 0; c < 32; c += 4) {
            float4 v = *(const float4*)(er + c);
            Ts[wr][c0 + c + 0] = v.x;
            Ts[wr][c0 + c + 1] = v.y;
            Ts[wr][c0 + c + 2] = v.z;
            Ts[wr][c0 + c + 3] = v.w;
        }
    }
    __syncthreads();

    float ds = 0.f;
    const int w  = t & 31;
    const int cg = t >> 5;
    const size_t basebh = (size_t)b * DDIM * HW + (size_t)h * 32;
    for (int c = cg; c < DDIM; c += 8) {
        float v = Ts[w][c];
        size_t gg = basebh + (size_t)c * HW + w;
        float zv = z[gg];
        out[gg] = v;
        float df = v - zv;
        ds += df * df;
    }
#pragma unroll
    for (int o = 16; o; o >>= 1) ds += __shfl_xor_sync(0xffffffffu, ds, o);
    if ((t & 31) == 0) spart[t >> 5] = ds;
    __syncthreads();
    if (t == 0) {
        float s = 0.f;
#pragma unroll
        for (int i = 0; i < 8; i++) s += spart[i];
        atomicAdd(&g_diff, (double)s);
    }
}

__global__ void k_final(float* __restrict__ out) {
    out[ZQ_ELEMS] = (float)(0.25 * g_diff / (double)ZQ_ELEMS);
}

extern "C" void kernel_launch(void* const* d_in, const int* in_sizes, int n_in,
                              void* d_out, int out_size) {
    const float* z   = (const float*)d_in[0];
    const float* emb = (const float*)d_in[1];
    float* out = (float*)d_out;

    cudaFuncSetAttribute(k_gemm,
                         cudaFuncAttributeMaxDynamicSharedMemorySize,
                         SMEM_ALLOC);

    k_prep<<<N_EMB / 8, 256>>>(emb);
    dim3 g(NQ / QT, SPLITS);
    k_gemm<<<g, 256, SMEM_ALLOC>>>(z);
    k_reduce<<<NQ / 256, 256>>>();
    k_refine<<<2048, 256>>>(z, emb);
    k_scatter<<<BB * (HW / 32), 256>>>(z, emb, out);
    k_final<<<1, 1>>>(out);
}

// round 12
// speedup vs baseline: 1.2172x; 1.2172x over previous
#include <cuda_runtime.h>
#include <cuda_fp16.h>
#include <cstdint>
#include <cfloat>

#define N_EMB   8192
#define DDIM    256
#define BB      32
#define HW      1024
#define NQ      32768
#define ZQ_ELEMS 8388608
#define SPLITS  8
#define KSPL    1024
#define QT      128
#define CCH     128
#define GCH     256
#define NST     32
#define TAU     0.20f

#define SM_A    0               // 128 q x 256 k halves, swizzled = 65536 B
#define SM_B    65536           // 2 stages x 16384 B
#define SM_EH   98304           // 1024 floats
#define SM_RED  106496          // rv1/ri1/rv2 3 x 2048 B
#define SMEM_ALLOC 112640

__device__ float  g_ehn[N_EMB];
__device__ __half g_eh[N_EMB * DDIM];
__device__ float  g_p1v[SPLITS * NQ];
__device__ int    g_p1i[SPLITS * NQ];
__device__ float  g_p2v[SPLITS * NQ];
__device__ float  g_cmin[GCH * NQ];
__device__ float  g_b1[NQ];
__device__ int    g_idx[NQ];
__device__ int    g_flag[NQ];
__device__ int    g_nflag;
__device__ int    g_sdone;
__device__ double g_diff;

__device__ __forceinline__ uint32_t smem_u32(const void* p) {
    uint32_t a;
    asm("{ .reg .u64 t; cvta.to.shared.u64 t, %1; cvt.u32.u64 %0, t; }"
        : "=r"(a) : "l"(p));
    return a;
}
__device__ __forceinline__ void cp16(uint32_t s, const void* g) {
    asm volatile("cp.async.cg.shared.global [%0], [%1], 16;"
                 :: "r"(s), "l"(g) : "memory");
}
#define CP_COMMIT() asm volatile("cp.async.commit_group;" ::: "memory")
#define CP_WAIT0()  asm volatile("cp.async.wait_group 0;" ::: "memory")

#define LDMX4(r0, r1, r2, r3, addr) \
    asm volatile("ldmatrix.sync.aligned.m8n8.x4.shared.b16 {%0,%1,%2,%3},[%4];" \
        : "=r"(r0), "=r"(r1), "=r"(r2), "=r"(r3) : "r"(addr))
#define MMA_F16(d, a, b0, b1) \
    asm volatile("mma.sync.aligned.m16n8k16.row.col.f32.f16.f16.f32 " \
        "{%0,%1,%2,%3},{%4,%5,%6,%7},{%8,%9},{%0,%1,%2,%3};" \
        : "+f"((d)[0]), "+f"((d)[1]), "+f"((d)[2]), "+f"((d)[3]) \
        : "r"((a)[0]), "r"((a)[1]), "r"((a)[2]), "r"((a)[3]), "r"(b0), "r"(b1))

__global__ void k_prep(const float* __restrict__ emb) {
    if (blockIdx.x == 0 && threadIdx.x == 0) {
        g_diff = 0.0; g_nflag = 0; g_sdone = 0;
    }
    int row  = blockIdx.x * 8 + (threadIdx.x >> 5);
    int lane = threadIdx.x & 31;
    const float4* e4 = (const float4*)(emb + (size_t)row * DDIM);
    __half2* eh2 = (__half2*)(g_eh + (size_t)row * DDIM);
    float s = 0.f;
    for (int i = lane; i < DDIM / 4; i += 32) {
        float4 v = e4[i];
        s += v.x * v.x + v.y * v.y + v.z * v.z + v.w * v.w;
        eh2[2 * i]     = __floats2half2_rn(v.x, v.y);
        eh2[2 * i + 1] = __floats2half2_rn(v.z, v.w);
    }
#pragma unroll
    for (int o = 16; o; o >>= 1) s += __shfl_xor_sync(0xffffffffu, s, o);
    if (lane == 0) g_ehn[row] = 0.5f * s;
}

// grid (NQ/QT=256, SPLITS=8), block 256 (8 warps: 2M x 4N), 2 CTAs/SM
__global__ void __launch_bounds__(256, 2)
k_gemm(const float* __restrict__ z) {
    extern __shared__ char sm[];
    const uint32_t smA = smem_u32(sm);
    float* ehs = (float*)(sm + SM_EH);
    float* rv1 = (float*)(sm + SM_RED);
    int*   ri1 = (int*)(sm + SM_RED + 2048);
    float* rv2 = (float*)(sm + SM_RED + 4096);

    const int tid = threadIdx.x, wid = tid >> 5, lane = tid & 31;
    const int warpM = wid >> 2, warpN = wid & 3;
    const int g = lane >> 2, t = lane & 3;
    const int qbase = blockIdx.x * QT, sp = blockIdx.y;
    const int bb = qbase / HW, nb = qbase % HW;
    const int kbase = sp * KSPL;

    for (int i = tid; i < KSPL; i += 256) ehs[i] = g_ehn[kbase + i];

    // A staging: z[128 q][256 k] -> half, swizzled [q][kblk^q]
    const float* zb = z + (size_t)bb * DDIM * HW + nb;
    for (int i = tid; i < QT * DDIM; i += 256) {
        int q = i & 127, k = i >> 7;
        __half hv = __float2half_rn(zb[(size_t)k * HW + q]);
        int kblk = k >> 3;
        uint32_t off = q * 512 + (((kblk & 24) | ((kblk ^ q) & 7)) << 4)
                     + (k & 7) * 2;
        *(__half*)(sm + off) = hv;
    }

    auto prefetch = [&](int s) {
        int cc = s >> 2, kb = s & 3, buf = s & 1;
        const __half* src = g_eh + (size_t)(kbase + cc * CCH) * DDIM + kb * 64;
        uint32_t dst = smA + 65536 + buf * 16384;
#pragma unroll
        for (int it = 0; it < 4; it++) {
            int idx = it * 256 + tid;
            int code = idx >> 3, kblk = idx & 7;
            cp16(dst + code * 128 + (((kblk ^ code) & 7) << 4),
                 src + (size_t)code * DDIM + kblk * 8);
        }
    };

    float D[4][4][4];
    float bv1[4][2], bv2[4][2];
    int   bix[4][2];
#pragma unroll
    for (int a = 0; a < 4; a++)
#pragma unroll
        for (int h = 0; h < 2; h++) {
            bv1[a][h] = FLT_MAX; bv2[a][h] = FLT_MAX; bix[a][h] = 0;
        }

    prefetch(0);
    CP_COMMIT();
    const int r_ld  = (lane & 7) | (lane & 8);   // A frag row
    const int cbhi  = (lane >> 4) & 1;           // A col halfblock
    const int bquad = lane >> 3, brow8 = lane & 7;  // B LDMX4 lane map

    for (int s = 0; s < NST; s++) {
        CP_WAIT0();
        __syncthreads();          // buf s ready AND all warps done with s-1
        if (s + 1 < NST) { prefetch(s + 1); CP_COMMIT(); }
        if ((s & 3) == 0) {
#pragma unroll
            for (int mt = 0; mt < 4; mt++)
#pragma unroll
                for (int nt = 0; nt < 4; nt++)
#pragma unroll
                    for (int c = 0; c < 4; c++) D[mt][nt][c] = 0.f;
        }
        const uint32_t bst = smA + 65536 + (s & 1) * 16384;
#pragma unroll
        for (int ks = 0; ks < 4; ks++) {
            const int kk = (s & 3) * 4 + ks;
            const int cb = kk * 2 + cbhi;
            uint32_t a[4][4];
#pragma unroll
            for (int mt = 0; mt < 4; mt++) {
                int mrow = warpM * 64 + mt * 16 + r_ld;
                uint32_t ad = smA + mrow * 512
                            + (((cb & 24) | ((cb ^ mrow) & 7)) << 4);
                LDMX4(a[mt][0], a[mt][1], a[mt][2], a[mt][3], ad);
            }
#pragma unroll
            for (int np = 0; np < 2; np++) {
                int code = warpN * 32 + (2 * np + (bquad >> 1)) * 8 + brow8;
                int kb2  = ks * 2 + (bquad & 1);
                uint32_t bad = bst + code * 128 + (((kb2 ^ code) & 7) << 4);
                uint32_t b0, b1, b2, b3;
                LDMX4(b0, b1, b2, b3, bad);
#pragma unroll
                for (int mt = 0; mt < 4; mt++) {
                    MMA_F16(D[mt][2 * np],     a[mt], b0, b1);
                    MMA_F16(D[mt][2 * np + 1], a[mt], b2, b3);
                }
            }
        }
        if ((s & 3) == 3) {
            const int cc = s >> 2;
            float eh[4][2];
#pragma unroll
            for (int nt = 0; nt < 4; nt++) {
                int cl = cc * CCH + warpN * 32 + nt * 8 + 2 * t;
                eh[nt][0] = ehs[cl]; eh[nt][1] = ehs[cl + 1];
            }
#pragma unroll
            for (int mt = 0; mt < 4; mt++)
#pragma unroll
                for (int h = 0; h < 2; h++) {
                    float cm = FLT_MAX;
#pragma unroll
                    for (int nt = 0; nt < 4; nt++)
#pragma unroll
                        for (int c = 0; c < 2; c++) {
                            float v = eh[nt][c] - D[mt][nt][h * 2 + c];
                            int gi = kbase + cc * CCH + warpN * 32 + nt * 8
                                   + 2 * t + c;
                            cm = fminf(cm, v);
                            if (v < bv1[mt][h] ||
                                (v == bv1[mt][h] && gi < bix[mt][h])) {
                                bv2[mt][h] = bv1[mt][h];
                                bv1[mt][h] = v; bix[mt][h] = gi;
                            } else {
                                bv2[mt][h] = fminf(bv2[mt][h], v);
                            }
                        }
                    cm = fminf(cm, __shfl_xor_sync(0xffffffffu, cm, 1));
                    cm = fminf(cm, __shfl_xor_sync(0xffffffffu, cm, 2));
                    if (t == 0) {
                        int slice = sp * 32 + cc * 4 + warpN;
                        int row = warpM * 64 + mt * 16 + h * 8 + g;
                        g_cmin[(size_t)slice * NQ + qbase + row] = cm;
                    }
                }
        }
    }
    __syncthreads();

#pragma unroll
    for (int mt = 0; mt < 4; mt++)
#pragma unroll
        for (int h = 0; h < 2; h++) {
            float v1 = bv1[mt][h], v2 = bv2[mt][h];
            int i1 = bix[mt][h];
#pragma unroll
            for (int o = 1; o <= 2; o <<= 1) {
                float pv1 = __shfl_xor_sync(0xffffffffu, v1, o);
                float pv2 = __shfl_xor_sync(0xffffffffu, v2, o);
                int   pi1 = __shfl_xor_sync(0xffffffffu, i1, o);
                if (pv1 < v1 || (pv1 == v1 && pi1 < i1)) {
                    v2 = fminf(v1, pv2); v1 = pv1; i1 = pi1;
                } else {
                    v2 = fminf(pv1, v2);
                }
            }
            if (t == 0) {
                int row = warpM * 64 + mt * 16 + h * 8 + g;
                rv1[row * 4 + warpN] = v1;
                ri1[row * 4 + warpN] = i1;
                rv2[row * 4 + warpN] = v2;
            }
        }
    __syncthreads();
    if (tid < 128) {
        float v1 = rv1[tid * 4]; int i1 = ri1[tid * 4]; float v2 = rv2[tid * 4];
#pragma unroll
        for (int wn = 1; wn < 4; wn++) {
            float pv1 = rv1[tid * 4 + wn], pv2 = rv2[tid * 4 + wn];
            int   pi1 = ri1[tid * 4 + wn];
            if (pv1 < v1 || (pv1 == v1 && pi1 < i1)) {
                v2 = fminf(v1, pv2); v1 = pv1; i1 = pi1;
            } else {
                v2 = fminf(pv1, v2);
            }
        }
        g_p1v[sp * NQ + qbase + tid] = v1;
        g_p1i[sp * NQ + qbase + tid] = i1;
        g_p2v[sp * NQ + qbase + tid] = v2;
    }
}

__global__ void k_reduce() {
    int q = blockIdx.x * 256 + threadIdx.x;
    float b1 = FLT_MAX, b2 = FLT_MAX;
    int i1 = 0;
#pragma unroll
    for (int s = 0; s < SPLITS; s++) {
        float v1 = g_p1v[s * NQ + q];
        int   ii = g_p1i[s * NQ + q];
        float v2 = g_p2v[s * NQ + q];
        if (v1 < b1) { b2 = b1; b1 = v1; i1 = ii; }
        else if (v1 < b2) b2 = v1;
        if (v2 < b2) b2 = v2;
    }
    g_idx[q] = i1;
    g_b1[q]  = b1;
    if (b2 - b1 <= TAU) {
        int p = atomicAdd(&g_nflag, 1);
        g_flag[p] = q;
    }
}

__global__ void __launch_bounds__(256, 2)
k_refine(const float* __restrict__ z, const float* __restrict__ emb) {
    __shared__ float zs[DDIM];
    __shared__ short clist[GCH];
    __shared__ int   ncand;
    __shared__ float wv[8];
    __shared__ int   wi[8];
    const int tid = threadIdx.x, wid = tid >> 5, lane = tid & 31;
    const int grp = lane >> 3, gl = lane & 7;
    const int nf = g_nflag;
    for (int fi = blockIdx.x; fi < nf; fi += gridDim.x) {
        const int q = g_flag[fi];
        if (tid == 0) ncand = 0;
        __syncthreads();
        zs[tid] = z[((size_t)(q >> 10) * DDIM + tid) * HW + (q & (HW - 1))];
        __syncthreads();
        float4 zr[8];
#pragma unroll
        for (int j = 0; j < 8; j++) zr[j] = *(const float4*)(zs + gl * 32 + j * 4);
        const float thr = g_b1[q] + TAU;
        if (tid < GCH && g_cmin[(size_t)tid * NQ + q] <= thr) {
            int p = atomicAdd(&ncand, 1);
            clist[p] = (short)tid;
        }
        __syncthreads();
        const int nc = ncand;
        float bv = FLT_MAX;
        int   bi = 0x7fffffff;
        for (int ci = 0; ci < nc; ci++) {
            const int code = clist[ci] * 32 + wid * 4 + grp;
            const float4* er = (const float4*)(emb + (size_t)code * DDIM + gl * 32);
            float s = 0.f;
#pragma unroll
            for (int j = 0; j < 8; j++) {
                float4 e = er[j];
                s += e.x * zr[j].x + e.y * zr[j].y + e.z * zr[j].z + e.w * zr[j].w;
            }
            s += __shfl_xor_sync(0xffffffffu, s, 1);
            s += __shfl_xor_sync(0xffffffffu, s, 2);
            s += __shfl_xor_sync(0xffffffffu, s, 4);
            float v = g_ehn[code] - s;
            if (v < bv || (v == bv && code < bi)) { bv = v; bi = code; }
        }
#pragma unroll
        for (int o = 8; o <= 16; o <<= 1) {
            float pv = __shfl_xor_sync(0xffffffffu, bv, o);
            int   pi = __shfl_xor_sync(0xffffffffu, bi, o);
            if (pv < bv || (pv == bv && pi < bi)) { bv = pv; bi = pi; }
        }
        if (lane == 0) { wv[wid] = bv; wi[wid] = bi; }
        __syncthreads();
        if (tid == 0) {
            float fv = wv[0]; int fx = wi[0];
#pragma unroll
            for (int w2 = 1; w2 < 8; w2++)
                if (wv[w2] < fv || (wv[w2] == fv && wi[w2] < fx)) {
                    fv = wv[w2]; fx = wi[w2];
                }
            g_idx[q] = fx;
        }
        __syncthreads();
    }
}

__global__ void k_scatter(const float* __restrict__ z,
                          const float* __restrict__ emb,
                          float* __restrict__ out) {
    __shared__ float Ts[32][257];
    __shared__ int   sidx[32];
    __shared__ float spart[8];
    const int bh = blockIdx.x;
    const int b  = bh >> 5;
    const int h  = bh & 31;
    const int t  = threadIdx.x;

    if (t < 32) {
        int ix = g_idx[b * HW + h * 32 + t];
        sidx[t] = ix;
        out[ZQ_ELEMS + 1 + b * HW + h * 32 + t] = (float)ix;
    }
    __syncthreads();
    {
        const int wr = t >> 3;
        const int c0 = (t & 7) * 32;
        const float* er = emb + (size_t)sidx[wr] * DDIM + c0;
        for (int c = 0; c < 32; c += 4) {
            float4 v = *(const float4*)(er + c);
            Ts[wr][c0 + c + 0] = v.x;
            Ts[wr][c0 + c + 1] = v.y;
            Ts[wr][c0 + c + 2] = v.z;
            Ts[wr][c0 + c + 3] = v.w;
        }
    }
    __syncthreads();

    float ds = 0.f;
    const int w  = t & 31;
    const int cg = t >> 5;
    const size_t basebh = (size_t)b * DDIM * HW + (size_t)h * 32;
    for (int c = cg; c < DDIM; c += 8) {
        float v = Ts[w][c];
        size_t gg = basebh + (size_t)c * HW + w;
        float zv = z[gg];
        out[gg] = v;
        float df = v - zv;
        ds += df * df;
    }
#pragma unroll
    for (int o = 16; o; o >>= 1) ds += __shfl_xor_sync(0xffffffffu, ds, o);
    if ((t & 31) == 0) spart[t >> 5] = ds;
    __syncthreads();
    if (t == 0) {
        float s = 0.f;
#pragma unroll
        for (int i = 0; i < 8; i++) s += spart[i];
        atomicAdd(&g_diff, (double)s);
        __threadfence();
        int done = atomicAdd(&g_sdone, 1);
        if (done == BB * (HW / 32) - 1) {
            double dsum = *((volatile double*)&g_diff);
            out[ZQ_ELEMS] = (float)(0.25 * dsum / (double)ZQ_ELEMS);
        }
    }
}

extern "C" void kernel_launch(void* const* d_in, const int* in_sizes, int n_in,
                              void* d_out, int out_size) {
    const float* z   = (const float*)d_in[0];
    const float* emb = (const float*)d_in[1];
    float* out = (float*)d_out;

    cudaFuncSetAttribute(k_gemm,
                         cudaFuncAttributeMaxDynamicSharedMemorySize,
                         SMEM_ALLOC);

    k_prep<<<N_EMB / 8, 256>>>(emb);
    dim3 g(NQ / QT, SPLITS);
    k_gemm<<<g, 256, SMEM_ALLOC>>>(z);
    k_reduce<<<NQ / 256, 256>>>();
    k_refine<<<2048, 256>>>(z, emb);
    k_scatter<<<BB * (HW / 32), 256>>>(z, emb, out);
}

// round 13
// speedup vs baseline: 1.2531x; 1.0295x over previous
#include <cuda_runtime.h>
#include <cuda_fp16.h>
#include <cstdint>
#include <cfloat>

#define N_EMB   8192
#define DDIM    256
#define BB      32
#define HW      1024
#define NQ      32768
#define ZQ_ELEMS 8388608
#define SPLITS  8
#define KSPL    1024
#define QT      128
#define CCH     128
#define GCH     256
#define NST     32
#define TAU     0.16f

#define SM_A    0               // 128 q x 256 k halves, swizzled = 65536 B
#define SM_B    65536           // 2 stages x 16384 B
#define SM_EH   98304           // 1024 floats
#define SM_RED  106496          // rv1/ri1/rv2 3 x 2048 B
#define SMEM_ALLOC 112640

__device__ float  g_ehn[N_EMB];
__device__ __half g_eh[N_EMB * DDIM];
__device__ float  g_p1v[SPLITS * NQ];
__device__ int    g_p1i[SPLITS * NQ];
__device__ float  g_p2v[SPLITS * NQ];
__device__ float  g_cmin[GCH * NQ];
__device__ float  g_b1[NQ];
__device__ int    g_idx[NQ];
__device__ int    g_flag[NQ];
__device__ int    g_nflag;
__device__ int    g_sdone;
__device__ double g_diff;

__device__ __forceinline__ uint32_t smem_u32(const void* p) {
    uint32_t a;
    asm("{ .reg .u64 t; cvta.to.shared.u64 t, %1; cvt.u32.u64 %0, t; }"
        : "=r"(a) : "l"(p));
    return a;
}
__device__ __forceinline__ void cp16(uint32_t s, const void* g) {
    asm volatile("cp.async.cg.shared.global [%0], [%1], 16;"
                 :: "r"(s), "l"(g) : "memory");
}
#define CP_COMMIT() asm volatile("cp.async.commit_group;" ::: "memory")
#define CP_WAIT0()  asm volatile("cp.async.wait_group 0;" ::: "memory")

#define LDMX4(r0, r1, r2, r3, addr) \
    asm volatile("ldmatrix.sync.aligned.m8n8.x4.shared.b16 {%0,%1,%2,%3},[%4];" \
        : "=r"(r0), "=r"(r1), "=r"(r2), "=r"(r3) : "r"(addr))
#define MMA_F16(d, a, b0, b1) \
    asm volatile("mma.sync.aligned.m16n8k16.row.col.f32.f16.f16.f32 " \
        "{%0,%1,%2,%3},{%4,%5,%6,%7},{%8,%9},{%0,%1,%2,%3};" \
        : "+f"((d)[0]), "+f"((d)[1]), "+f"((d)[2]), "+f"((d)[3]) \
        : "r"((a)[0]), "r"((a)[1]), "r"((a)[2]), "r"((a)[3]), "r"(b0), "r"(b1))

__global__ void k_prep(const float* __restrict__ emb) {
    if (blockIdx.x == 0 && threadIdx.x == 0) {
        g_diff = 0.0; g_nflag = 0; g_sdone = 0;
    }
    int row  = blockIdx.x * 8 + (threadIdx.x >> 5);
    int lane = threadIdx.x & 31;
    const float4* e4 = (const float4*)(emb + (size_t)row * DDIM);
    __half2* eh2 = (__half2*)(g_eh + (size_t)row * DDIM);
    float s = 0.f;
    for (int i = lane; i < DDIM / 4; i += 32) {
        float4 v = e4[i];
        s += v.x * v.x + v.y * v.y + v.z * v.z + v.w * v.w;
        eh2[2 * i]     = __floats2half2_rn(v.x, v.y);
        eh2[2 * i + 1] = __floats2half2_rn(v.z, v.w);
    }
#pragma unroll
    for (int o = 16; o; o >>= 1) s += __shfl_xor_sync(0xffffffffu, s, o);
    if (lane == 0) g_ehn[row] = 0.5f * s;
}

// grid (NQ/QT=256, SPLITS=8), block 256 (8 warps: 2M x 4N), 2 CTAs/SM
__global__ void __launch_bounds__(256, 2)
k_gemm(const float* __restrict__ z) {
    extern __shared__ char sm[];
    const uint32_t smA = smem_u32(sm);
    float* ehs = (float*)(sm + SM_EH);
    float* rv1 = (float*)(sm + SM_RED);
    int*   ri1 = (int*)(sm + SM_RED + 2048);
    float* rv2 = (float*)(sm + SM_RED + 4096);

    const int tid = threadIdx.x, wid = tid >> 5, lane = tid & 31;
    const int warpM = wid >> 2, warpN = wid & 3;
    const int g = lane >> 2, t = lane & 3;
    const int qbase = blockIdx.x * QT, sp = blockIdx.y;
    const int bb = qbase / HW, nb = qbase % HW;
    const int kbase = sp * KSPL;

    for (int i = tid; i < KSPL; i += 256) ehs[i] = g_ehn[kbase + i];

    // A staging: z[128 q][256 k] -> half, swizzled [q][kblk^q]
    const float* zb = z + (size_t)bb * DDIM * HW + nb;
    for (int i = tid; i < QT * DDIM; i += 256) {
        int q = i & 127, k = i >> 7;
        __half hv = __float2half_rn(zb[(size_t)k * HW + q]);
        int kblk = k >> 3;
        uint32_t off = q * 512 + (((kblk & 24) | ((kblk ^ q) & 7)) << 4)
                     + (k & 7) * 2;
        *(__half*)(sm + off) = hv;
    }

    auto prefetch = [&](int s) {
        int cc = s >> 2, kb = s & 3, buf = s & 1;
        const __half* src = g_eh + (size_t)(kbase + cc * CCH) * DDIM + kb * 64;
        uint32_t dst = smA + 65536 + buf * 16384;
#pragma unroll
        for (int it = 0; it < 4; it++) {
            int idx = it * 256 + tid;
            int code = idx >> 3, kblk = idx & 7;
            cp16(dst + code * 128 + (((kblk ^ code) & 7) << 4),
                 src + (size_t)code * DDIM + kblk * 8);
        }
    };

    float D[4][4][4];
    float bv1[4][2], bv2[4][2];
    int   bix[4][2];
#pragma unroll
    for (int a = 0; a < 4; a++)
#pragma unroll
        for (int h = 0; h < 2; h++) {
            bv1[a][h] = FLT_MAX; bv2[a][h] = FLT_MAX; bix[a][h] = 0;
        }

    prefetch(0);
    CP_COMMIT();
    const int r_ld  = (lane & 7) | (lane & 8);   // A frag row
    const int cbhi  = (lane >> 4) & 1;           // A col halfblock
    const int bquad = lane >> 3, brow8 = lane & 7;  // B LDMX4 lane map

    for (int s = 0; s < NST; s++) {
        CP_WAIT0();
        __syncthreads();          // buf s ready AND all warps done with s-1
        if (s + 1 < NST) { prefetch(s + 1); CP_COMMIT(); }
        if ((s & 3) == 0) {
#pragma unroll
            for (int mt = 0; mt < 4; mt++)
#pragma unroll
                for (int nt = 0; nt < 4; nt++)
#pragma unroll
                    for (int c = 0; c < 4; c++) D[mt][nt][c] = 0.f;
        }
        const uint32_t bst = smA + 65536 + (s & 1) * 16384;
#pragma unroll
        for (int ks = 0; ks < 4; ks++) {
            const int kk = (s & 3) * 4 + ks;
            const int cb = kk * 2 + cbhi;
            uint32_t a[4][4];
#pragma unroll
            for (int mt = 0; mt < 4; mt++) {
                int mrow = warpM * 64 + mt * 16 + r_ld;
                uint32_t ad = smA + mrow * 512
                            + (((cb & 24) | ((cb ^ mrow) & 7)) << 4);
                LDMX4(a[mt][0], a[mt][1], a[mt][2], a[mt][3], ad);
            }
#pragma unroll
            for (int np = 0; np < 2; np++) {
                int code = warpN * 32 + (2 * np + (bquad >> 1)) * 8 + brow8;
                int kb2  = ks * 2 + (bquad & 1);
                uint32_t bad = bst + code * 128 + (((kb2 ^ code) & 7) << 4);
                uint32_t b0, b1, b2, b3;
                LDMX4(b0, b1, b2, b3, bad);
#pragma unroll
                for (int mt = 0; mt < 4; mt++) {
                    MMA_F16(D[mt][2 * np],     a[mt], b0, b1);
                    MMA_F16(D[mt][2 * np + 1], a[mt], b2, b3);
                }
            }
        }
        if ((s & 3) == 3) {
            const int cc = s >> 2;
            float eh[4][2];
#pragma unroll
            for (int nt = 0; nt < 4; nt++) {
                int cl = cc * CCH + warpN * 32 + nt * 8 + 2 * t;
                eh[nt][0] = ehs[cl]; eh[nt][1] = ehs[cl + 1];
            }
#pragma unroll
            for (int mt = 0; mt < 4; mt++)
#pragma unroll
                for (int h = 0; h < 2; h++) {
                    float cm = FLT_MAX;
#pragma unroll
                    for (int nt = 0; nt < 4; nt++)
#pragma unroll
                        for (int c = 0; c < 2; c++) {
                            float v = eh[nt][c] - D[mt][nt][h * 2 + c];
                            int gi = kbase + cc * CCH + warpN * 32 + nt * 8
                                   + 2 * t + c;
                            cm = fminf(cm, v);
                            if (v < bv1[mt][h] ||
                                (v == bv1[mt][h] && gi < bix[mt][h])) {
                                bv2[mt][h] = bv1[mt][h];
                                bv1[mt][h] = v; bix[mt][h] = gi;
                            } else {
                                bv2[mt][h] = fminf(bv2[mt][h], v);
                            }
                        }
                    cm = fminf(cm, __shfl_xor_sync(0xffffffffu, cm, 1));
                    cm = fminf(cm, __shfl_xor_sync(0xffffffffu, cm, 2));
                    if (t == 0) {
                        int slice = sp * 32 + cc * 4 + warpN;
                        int row = warpM * 64 + mt * 16 + h * 8 + g;
                        g_cmin[(size_t)slice * NQ + qbase + row] = cm;
                    }
                }
        }
    }
    __syncthreads();

#pragma unroll
    for (int mt = 0; mt < 4; mt++)
#pragma unroll
        for (int h = 0; h < 2; h++) {
            float v1 = bv1[mt][h], v2 = bv2[mt][h];
            int i1 = bix[mt][h];
#pragma unroll
            for (int o = 1; o <= 2; o <<= 1) {
                float pv1 = __shfl_xor_sync(0xffffffffu, v1, o);
                float pv2 = __shfl_xor_sync(0xffffffffu, v2, o);
                int   pi1 = __shfl_xor_sync(0xffffffffu, i1, o);
                if (pv1 < v1 || (pv1 == v1 && pi1 < i1)) {
                    v2 = fminf(v1, pv2); v1 = pv1; i1 = pi1;
                } else {
                    v2 = fminf(pv1, v2);
                }
            }
            if (t == 0) {
                int row = warpM * 64 + mt * 16 + h * 8 + g;
                rv1[row * 4 + warpN] = v1;
                ri1[row * 4 + warpN] = i1;
                rv2[row * 4 + warpN] = v2;
            }
        }
    __syncthreads();
    if (tid < 128) {
        float v1 = rv1[tid * 4]; int i1 = ri1[tid * 4]; float v2 = rv2[tid * 4];
#pragma unroll
        for (int wn = 1; wn < 4; wn++) {
            float pv1 = rv1[tid * 4 + wn], pv2 = rv2[tid * 4 + wn];
            int   pi1 = ri1[tid * 4 + wn];
            if (pv1 < v1 || (pv1 == v1 && pi1 < i1)) {
                v2 = fminf(v1, pv2); v1 = pv1; i1 = pi1;
            } else {
                v2 = fminf(pv1, v2);
            }
        }
        g_p1v[sp * NQ + qbase + tid] = v1;
        g_p1i[sp * NQ + qbase + tid] = i1;
        g_p2v[sp * NQ + qbase + tid] = v2;
    }
}

__global__ void k_reduce() {
    int q = blockIdx.x * 256 + threadIdx.x;
    float b1 = FLT_MAX, b2 = FLT_MAX;
    int i1 = 0;
#pragma unroll
    for (int s = 0; s < SPLITS; s++) {
        float v1 = g_p1v[s * NQ + q];
        int   ii = g_p1i[s * NQ + q];
        float v2 = g_p2v[s * NQ + q];
        if (v1 < b1) { b2 = b1; b1 = v1; i1 = ii; }
        else if (v1 < b2) b2 = v1;
        if (v2 < b2) b2 = v2;
    }
    g_idx[q] = i1;
    g_b1[q]  = b1;
    if (b2 - b1 <= TAU) {
        int p = atomicAdd(&g_nflag, 1);
        g_flag[p] = q;
    }
}

__global__ void __launch_bounds__(256, 2)
k_refine(const float* __restrict__ z, const float* __restrict__ emb) {
    __shared__ float zs[DDIM];
    __shared__ short clist[GCH];
    __shared__ int   ncand;
    __shared__ float wv[8];
    __shared__ int   wi[8];
    const int tid = threadIdx.x, wid = tid >> 5, lane = tid & 31;
    const int grp = lane >> 3, gl = lane & 7;
    const int nf = g_nflag;
    for (int fi = blockIdx.x; fi < nf; fi += gridDim.x) {
        const int q = g_flag[fi];
        if (tid == 0) ncand = 0;
        __syncthreads();
        zs[tid] = z[((size_t)(q >> 10) * DDIM + tid) * HW + (q & (HW - 1))];
        __syncthreads();
        float4 zr[8];
#pragma unroll
        for (int j = 0; j < 8; j++) zr[j] = *(const float4*)(zs + gl * 32 + j * 4);
        const float thr = g_b1[q] + TAU;
        if (tid < GCH && g_cmin[(size_t)tid * NQ + q] <= thr) {
            int p = atomicAdd(&ncand, 1);
            clist[p] = (short)tid;
        }
        __syncthreads();
        const int nc = ncand;
        float bv = FLT_MAX;
        int   bi = 0x7fffffff;
        for (int ci = 0; ci < nc; ci++) {
            const int code = clist[ci] * 32 + wid * 4 + grp;
            const float4* er = (const float4*)(emb + (size_t)code * DDIM + gl * 32);
            float s = 0.f;
#pragma unroll
            for (int j = 0; j < 8; j++) {
                float4 e = er[j];
                s += e.x * zr[j].x + e.y * zr[j].y + e.z * zr[j].z + e.w * zr[j].w;
            }
            s += __shfl_xor_sync(0xffffffffu, s, 1);
            s += __shfl_xor_sync(0xffffffffu, s, 2);
            s += __shfl_xor_sync(0xffffffffu, s, 4);
            float v = g_ehn[code] - s;
            if (v < bv || (v == bv && code < bi)) { bv = v; bi = code; }
        }
#pragma unroll
        for (int o = 8; o <= 16; o <<= 1) {
            float pv = __shfl_xor_sync(0xffffffffu, bv, o);
            int   pi = __shfl_xor_sync(0xffffffffu, bi, o);
            if (pv < bv || (pv == bv && pi < bi)) { bv = pv; bi = pi; }
        }
        if (lane == 0) { wv[wid] = bv; wi[wid] = bi; }
        __syncthreads();
        if (tid == 0) {
            float fv = wv[0]; int fx = wi[0];
#pragma unroll
            for (int w2 = 1; w2 < 8; w2++)
                if (wv[w2] < fv || (wv[w2] == fv && wi[w2] < fx)) {
                    fv = wv[w2]; fx = wi[w2];
                }
            g_idx[q] = fx;
        }
        __syncthreads();
    }
}

__global__ void k_scatter(const float* __restrict__ z,
                          const float* __restrict__ emb,
                          float* __restrict__ out) {
    __shared__ float Ts[32][257];
    __shared__ int   sidx[32];
    __shared__ float spart[8];
    const int bh = blockIdx.x;
    const int b  = bh >> 5;
    const int h  = bh & 31;
    const int t  = threadIdx.x;

    if (t < 32) {
        int ix = g_idx[b * HW + h * 32 + t];
        sidx[t] = ix;
        out[ZQ_ELEMS + 1 + b * HW + h * 32 + t] = (float)ix;
    }
    __syncthreads();
    {
        const int wr = t >> 3;
        const int c0 = (t & 7) * 32;
        const float* er = emb + (size_t)sidx[wr] * DDIM + c0;
        for (int c = 0; c < 32; c += 4) {
            float4 v = *(const float4*)(er + c);
            Ts[wr][c0 + c + 0] = v.x;
            Ts[wr][c0 + c + 1] = v.y;
            Ts[wr][c0 + c + 2] = v.z;
            Ts[wr][c0 + c + 3] = v.w;
        }
    }
    __syncthreads();

    float ds = 0.f;
    const int w4  = (t & 7) * 4;
    const int c00 = t >> 3;
    const size_t basebh = (size_t)b * DDIM * HW + (size_t)h * 32;
#pragma unroll
    for (int it = 0; it < 8; it++) {
        int c = c00 + it * 32;
        float4 v;
        v.x = Ts[w4 + 0][c];
        v.y = Ts[w4 + 1][c];
        v.z = Ts[w4 + 2][c];
        v.w = Ts[w4 + 3][c];
        size_t gg = basebh + (size_t)c * HW + w4;
        float4 zv = *(const float4*)(z + gg);
        *(float4*)(out + gg) = v;
        float d0 = v.x - zv.x, d1 = v.y - zv.y;
        float d2 = v.z - zv.z, d3 = v.w - zv.w;
        ds += d0 * d0 + d1 * d1 + d2 * d2 + d3 * d3;
    }
#pragma unroll
    for (int o = 16; o; o >>= 1) ds += __shfl_xor_sync(0xffffffffu, ds, o);
    if ((t & 31) == 0) spart[t >> 5] = ds;
    __syncthreads();
    if (t == 0) {
        float s = 0.f;
#pragma unroll
        for (int i = 0; i < 8; i++) s += spart[i];
        atomicAdd(&g_diff, (double)s);
        __threadfence();
        int done = atomicAdd(&g_sdone, 1);
        if (done == BB * (HW / 32) - 1) {
            double dsum = *((volatile double*)&g_diff);
            out[ZQ_ELEMS] = (float)(0.25 * dsum / (double)ZQ_ELEMS);
        }
    }
}

extern "C" void kernel_launch(void* const* d_in, const int* in_sizes, int n_in,
                              void* d_out, int out_size) {
    const float* z   = (const float*)d_in[0];
    const float* emb = (const float*)d_in[1];
    float* out = (float*)d_out;

    cudaFuncSetAttribute(k_gemm,
                         cudaFuncAttributeMaxDynamicSharedMemorySize,
                         SMEM_ALLOC);

    k_prep<<<N_EMB / 8, 256>>>(emb);
    dim3 g(NQ / QT, SPLITS);
    k_gemm<<<g, 256, SMEM_ALLOC>>>(z);
    k_reduce<<<NQ / 256, 256>>>();
    k_refine<<<2048, 256>>>(z, emb);
    k_scatter<<<BB * (HW / 32), 256>>>(z, emb, out);
}

// round 14
// speedup vs baseline: 1.2643x; 1.0090x over previous
#include <cuda_runtime.h>
#include <cuda_fp16.h>
#include <cstdint>
#include <cfloat>

#define N_EMB   8192
#define DDIM    256
#define BB      32
#define HW      1024
#define NQ      32768
#define ZQ_ELEMS 8388608
#define SPLITS  8
#define KSPL    1024
#define QT      128
#define CCH     128
#define GCH     256
#define NST     32
#define TAU     0.16f

#define SM_A    0               // 128 q x 256 k halves, swizzled = 65536 B
#define SM_B    65536           // 2 stages x 16384 B
#define SM_EH   98304           // 1024 floats
#define SM_RED  106496          // rv1/ri1/rv2 3 x 2048 B
#define SMEM_ALLOC 112640

__device__ float  g_ehn[N_EMB];
__device__ __half g_eh[N_EMB * DDIM];
__device__ float  g_p1v[SPLITS * NQ];
__device__ int    g_p1i[SPLITS * NQ];
__device__ float  g_p2v[SPLITS * NQ];
__device__ float  g_cmin[GCH * NQ];
__device__ float  g_b1[NQ];
__device__ int    g_idx[NQ];
__device__ int    g_flag[NQ];
__device__ int    g_nflag;
__device__ int    g_sdone;
__device__ double g_diff;

__device__ __forceinline__ uint32_t smem_u32(const void* p) {
    uint32_t a;
    asm("{ .reg .u64 t; cvta.to.shared.u64 t, %1; cvt.u32.u64 %0, t; }"
        : "=r"(a) : "l"(p));
    return a;
}
__device__ __forceinline__ void cp16(uint32_t s, const void* g) {
    asm volatile("cp.async.cg.shared.global [%0], [%1], 16;"
                 :: "r"(s), "l"(g) : "memory");
}
#define CP_COMMIT() asm volatile("cp.async.commit_group;" ::: "memory")
#define CP_WAIT0()  asm volatile("cp.async.wait_group 0;" ::: "memory")
#define BARX(id, n) asm volatile("bar.sync %0, %1;" :: "r"(id), "r"(n) : "memory")

#define LDMX4(r0, r1, r2, r3, addr) \
    asm volatile("ldmatrix.sync.aligned.m8n8.x4.shared.b16 {%0,%1,%2,%3},[%4];" \
        : "=r"(r0), "=r"(r1), "=r"(r2), "=r"(r3) : "r"(addr))
#define MMA_F16(d, a, b0, b1) \
    asm volatile("mma.sync.aligned.m16n8k16.row.col.f32.f16.f16.f32 " \
        "{%0,%1,%2,%3},{%4,%5,%6,%7},{%8,%9},{%0,%1,%2,%3};" \
        : "+f"((d)[0]), "+f"((d)[1]), "+f"((d)[2]), "+f"((d)[3]) \
        : "r"((a)[0]), "r"((a)[1]), "r"((a)[2]), "r"((a)[3]), "r"(b0), "r"(b1))

__global__ void k_prep(const float* __restrict__ emb) {
    if (blockIdx.x == 0 && threadIdx.x == 0) {
        g_diff = 0.0; g_nflag = 0; g_sdone = 0;
    }
    int row  = blockIdx.x * 8 + (threadIdx.x >> 5);
    int lane = threadIdx.x & 31;
    const float4* e4 = (const float4*)(emb + (size_t)row * DDIM);
    __half2* eh2 = (__half2*)(g_eh + (size_t)row * DDIM);
    float s = 0.f;
    for (int i = lane; i < DDIM / 4; i += 32) {
        float4 v = e4[i];
        s += v.x * v.x + v.y * v.y + v.z * v.z + v.w * v.w;
        eh2[2 * i]     = __floats2half2_rn(v.x, v.y);
        eh2[2 * i + 1] = __floats2half2_rn(v.z, v.w);
    }
#pragma unroll
    for (int o = 16; o; o >>= 1) s += __shfl_xor_sync(0xffffffffu, s, o);
    if (lane == 0) g_ehn[row] = 0.5f * s;
}

// grid (NQ/QT=256, SPLITS=8), block 256 (8 warps: 2M x 4N), 2 CTAs/SM
__global__ void __launch_bounds__(256, 2)
k_gemm(const float* __restrict__ z) {
    extern __shared__ char sm[];
    const uint32_t smA = smem_u32(sm);
    float* ehs = (float*)(sm + SM_EH);
    float* rv1 = (float*)(sm + SM_RED);
    int*   ri1 = (int*)(sm + SM_RED + 2048);
    float* rv2 = (float*)(sm + SM_RED + 4096);

    const int tid = threadIdx.x, wid = tid >> 5, lane = tid & 31;
    const int warpM = wid >> 2, warpN = wid & 3;
    const int g = lane >> 2, t = lane & 3;
    const int qbase = blockIdx.x * QT, sp = blockIdx.y;
    const int bb = qbase / HW, nb = qbase % HW;
    const int kbase = sp * KSPL;

    for (int i = tid; i < KSPL; i += 256) ehs[i] = g_ehn[kbase + i];

    // A staging: z[128 q][256 k] -> half, swizzled [q][kblk^q]
    const float* zb = z + (size_t)bb * DDIM * HW + nb;
    for (int i = tid; i < QT * DDIM; i += 256) {
        int q = i & 127, k = i >> 7;
        __half hv = __float2half_rn(zb[(size_t)k * HW + q]);
        int kblk = k >> 3;
        uint32_t off = q * 512 + (((kblk & 24) | ((kblk ^ q) & 7)) << 4)
                     + (k & 7) * 2;
        *(__half*)(sm + off) = hv;
    }

    auto prefetch = [&](int s) {
        int cc = s >> 2, kb = s & 3, buf = s & 1;
        const __half* src = g_eh + (size_t)(kbase + cc * CCH) * DDIM + kb * 64;
        uint32_t dst = smA + 65536 + buf * 16384;
#pragma unroll
        for (int it = 0; it < 4; it++) {
            int idx = it * 256 + tid;
            int code = idx >> 3, kblk = idx & 7;
            cp16(dst + code * 128 + (((kblk ^ code) & 7) << 4),
                 src + (size_t)code * DDIM + kblk * 8);
        }
    };

    float D[4][4][4];
    float bv1[4][2], bv2[4][2];
    int   bix[4][2];
#pragma unroll
    for (int a = 0; a < 4; a++)
#pragma unroll
        for (int h = 0; h < 2; h++) {
            bv1[a][h] = FLT_MAX; bv2[a][h] = FLT_MAX; bix[a][h] = 0;
        }

    prefetch(0);
    CP_COMMIT();
    const int r_ld  = (lane & 7) | (lane & 8);   // A frag row
    const int cbhi  = (lane >> 4) & 1;           // A col halfblock
    const int bquad = lane >> 3, brow8 = lane & 7;  // B LDMX4 lane map

    for (int s = 0; s < NST; s++) {
        CP_WAIT0();
        __syncthreads();          // buf s ready AND all warps done with s-1
        if (s + 1 < NST) { prefetch(s + 1); CP_COMMIT(); }
        if ((s & 3) == 0) {
#pragma unroll
            for (int mt = 0; mt < 4; mt++)
#pragma unroll
                for (int nt = 0; nt < 4; nt++)
#pragma unroll
                    for (int c = 0; c < 4; c++) D[mt][nt][c] = 0.f;
        }
        const uint32_t bst = smA + 65536 + (s & 1) * 16384;
#pragma unroll
        for (int ks = 0; ks < 4; ks++) {
            const int kk = (s & 3) * 4 + ks;
            const int cb = kk * 2 + cbhi;
            uint32_t a[4][4];
#pragma unroll
            for (int mt = 0; mt < 4; mt++) {
                int mrow = warpM * 64 + mt * 16 + r_ld;
                uint32_t ad = smA + mrow * 512
                            + (((cb & 24) | ((cb ^ mrow) & 7)) << 4);
                LDMX4(a[mt][0], a[mt][1], a[mt][2], a[mt][3], ad);
            }
#pragma unroll
            for (int np = 0; np < 2; np++) {
                int code = warpN * 32 + (2 * np + (bquad >> 1)) * 8 + brow8;
                int kb2  = ks * 2 + (bquad & 1);
                uint32_t bad = bst + code * 128 + (((kb2 ^ code) & 7) << 4);
                uint32_t b0, b1, b2, b3;
                LDMX4(b0, b1, b2, b3, bad);
#pragma unroll
                for (int mt = 0; mt < 4; mt++) {
                    MMA_F16(D[mt][2 * np],     a[mt], b0, b1);
                    MMA_F16(D[mt][2 * np + 1], a[mt], b2, b3);
                }
            }
        }
        if ((s & 3) == 3) {
            const int cc = s >> 2;
            float eh[4][2];
#pragma unroll
            for (int nt = 0; nt < 4; nt++) {
                int cl = cc * CCH + warpN * 32 + nt * 8 + 2 * t;
                eh[nt][0] = ehs[cl]; eh[nt][1] = ehs[cl + 1];
            }
#pragma unroll
            for (int mt = 0; mt < 4; mt++)
#pragma unroll
                for (int h = 0; h < 2; h++) {
                    float cm = FLT_MAX;
#pragma unroll
                    for (int nt = 0; nt < 4; nt++)
#pragma unroll
                        for (int c = 0; c < 2; c++) {
                            float v = eh[nt][c] - D[mt][nt][h * 2 + c];
                            int gi = kbase + cc * CCH + warpN * 32 + nt * 8
                                   + 2 * t + c;
                            cm = fminf(cm, v);
                            if (v < bv1[mt][h] ||
                                (v == bv1[mt][h] && gi < bix[mt][h])) {
                                bv2[mt][h] = bv1[mt][h];
                                bv1[mt][h] = v; bix[mt][h] = gi;
                            } else {
                                bv2[mt][h] = fminf(bv2[mt][h], v);
                            }
                        }
                    cm = fminf(cm, __shfl_xor_sync(0xffffffffu, cm, 1));
                    cm = fminf(cm, __shfl_xor_sync(0xffffffffu, cm, 2));
                    if (t == 0) {
                        int slice = sp * 32 + cc * 4 + warpN;
                        int row = warpM * 64 + mt * 16 + h * 8 + g;
                        g_cmin[(size_t)slice * NQ + qbase + row] = cm;
                    }
                }
        }
    }
    __syncthreads();

#pragma unroll
    for (int mt = 0; mt < 4; mt++)
#pragma unroll
        for (int h = 0; h < 2; h++) {
            float v1 = bv1[mt][h], v2 = bv2[mt][h];
            int i1 = bix[mt][h];
#pragma unroll
            for (int o = 1; o <= 2; o <<= 1) {
                float pv1 = __shfl_xor_sync(0xffffffffu, v1, o);
                float pv2 = __shfl_xor_sync(0xffffffffu, v2, o);
                int   pi1 = __shfl_xor_sync(0xffffffffu, i1, o);
                if (pv1 < v1 || (pv1 == v1 && pi1 < i1)) {
                    v2 = fminf(v1, pv2); v1 = pv1; i1 = pi1;
                } else {
                    v2 = fminf(pv1, v2);
                }
            }
            if (t == 0) {
                int row = warpM * 64 + mt * 16 + h * 8 + g;
                rv1[row * 4 + warpN] = v1;
                ri1[row * 4 + warpN] = i1;
                rv2[row * 4 + warpN] = v2;
            }
        }
    __syncthreads();
    if (tid < 128) {
        float v1 = rv1[tid * 4]; int i1 = ri1[tid * 4]; float v2 = rv2[tid * 4];
#pragma unroll
        for (int wn = 1; wn < 4; wn++) {
            float pv1 = rv1[tid * 4 + wn], pv2 = rv2[tid * 4 + wn];
            int   pi1 = ri1[tid * 4 + wn];
            if (pv1 < v1 || (pv1 == v1 && pi1 < i1)) {
                v2 = fminf(v1, pv2); v1 = pv1; i1 = pi1;
            } else {
                v2 = fminf(pv1, v2);
            }
        }
        g_p1v[sp * NQ + qbase + tid] = v1;
        g_p1i[sp * NQ + qbase + tid] = i1;
        g_p2v[sp * NQ + qbase + tid] = v2;
    }
}

__global__ void k_reduce() {
    int q = blockIdx.x * 256 + threadIdx.x;
    float b1 = FLT_MAX, b2 = FLT_MAX;
    int i1 = 0;
#pragma unroll
    for (int s = 0; s < SPLITS; s++) {
        float v1 = g_p1v[s * NQ + q];
        int   ii = g_p1i[s * NQ + q];
        float v2 = g_p2v[s * NQ + q];
        if (v1 < b1) { b2 = b1; b1 = v1; i1 = ii; }
        else if (v1 < b2) b2 = v1;
        if (v2 < b2) b2 = v2;
    }
    g_idx[q] = i1;
    g_b1[q]  = b1;
    if (b2 - b1 <= TAU) {
        int p = atomicAdd(&g_nflag, 1);
        g_flag[p] = q;
    }
}

// Two independent 128-thread groups per block, each refining its own query.
__global__ void __launch_bounds__(256, 2)
k_refine(const float* __restrict__ z, const float* __restrict__ emb) {
    __shared__ float zs[2][DDIM];
    __shared__ short clist[2][GCH];
    __shared__ int   ncand[2];
    __shared__ float wv[2][4];
    __shared__ int   wi[2][4];
    const int tid  = threadIdx.x;
    const int gsel = tid >> 7;          // group 0 or 1
    const int ltid = tid & 127;
    const int lwid = (tid >> 5) & 3;    // warp within group
    const int lane = tid & 31;
    const int grp8 = lane >> 3, gl = lane & 7;
    const int nf = g_nflag;
    if (nf == 0) return;
    const int bar = 1 + gsel;

    for (int base = blockIdx.x * 2; base < nf; base += gridDim.x * 2) {
        const int fi = base + gsel;
        const bool active = fi < nf;
        const int q = active ? g_flag[fi] : g_flag[0];
        if (ltid == 0) ncand[gsel] = 0;
        BARX(bar, 128);
        // load z row (256 dims, 128 threads -> 2 each)
        {
            const float* zq = z + ((size_t)(q >> 10) * DDIM) * HW + (q & (HW - 1));
            zs[gsel][ltid]       = zq[(size_t)ltid * HW];
            zs[gsel][ltid + 128] = zq[(size_t)(ltid + 128) * HW];
        }
        // candidate slices (256 slices, 128 threads -> 2 each)
        const float thr = g_b1[q] + TAU;
#pragma unroll
        for (int hh = 0; hh < 2; hh++) {
            int sl = ltid + hh * 128;
            if (g_cmin[(size_t)sl * NQ + q] <= thr) {
                int p = atomicAdd(&ncand[gsel], 1);
                clist[gsel][p] = (short)sl;
            }
        }
        BARX(bar, 128);
        float4 zr[8];
#pragma unroll
        for (int j = 0; j < 8; j++)
            zr[j] = *(const float4*)(&zs[gsel][gl * 32 + j * 4]);
        const int nc = ncand[gsel];
        float bv = FLT_MAX;
        int   bi = 0x7fffffff;
        for (int ci = 0; ci < nc; ci++) {
            const int cb = clist[gsel][ci] * 32 + lwid * 8 + grp8;
#pragma unroll
            for (int p2 = 0; p2 < 2; p2++) {
                const int code = cb + p2 * 4;
                const float4* er =
                    (const float4*)(emb + (size_t)code * DDIM + gl * 32);
                float s = 0.f;
#pragma unroll
                for (int j = 0; j < 8; j++) {
                    float4 e = er[j];
                    s += e.x * zr[j].x + e.y * zr[j].y
                       + e.z * zr[j].z + e.w * zr[j].w;
                }
                s += __shfl_xor_sync(0xffffffffu, s, 1);
                s += __shfl_xor_sync(0xffffffffu, s, 2);
                s += __shfl_xor_sync(0xffffffffu, s, 4);
                float v = g_ehn[code] - s;
                if (v < bv || (v == bv && code < bi)) { bv = v; bi = code; }
            }
        }
        // reduce across the 4 grp8 units in this warp
#pragma unroll
        for (int o = 8; o <= 16; o <<= 1) {
            float pv = __shfl_xor_sync(0xffffffffu, bv, o);
            int   pi = __shfl_xor_sync(0xffffffffu, bi, o);
            if (pv < bv || (pv == bv && pi < bi)) { bv = pv; bi = pi; }
        }
        if (lane == 0) { wv[gsel][lwid] = bv; wi[gsel][lwid] = bi; }
        BARX(bar, 128);
        if (ltid == 0 && active) {
            float fv = wv[gsel][0]; int fx = wi[gsel][0];
#pragma unroll
            for (int w2 = 1; w2 < 4; w2++)
                if (wv[gsel][w2] < fv ||
                    (wv[gsel][w2] == fv && wi[gsel][w2] < fx)) {
                    fv = wv[gsel][w2]; fx = wi[gsel][w2];
                }
            g_idx[q] = fx;
        }
        BARX(bar, 128);
    }
}

__global__ void k_scatter(const float* __restrict__ z,
                          const float* __restrict__ emb,
                          float* __restrict__ out) {
    __shared__ float Ts[32][257];
    __shared__ int   sidx[32];
    __shared__ float spart[8];
    const int bh = blockIdx.x;
    const int b  = bh >> 5;
    const int h  = bh & 31;
    const int t  = threadIdx.x;

    if (t < 32) {
        int ix = g_idx[b * HW + h * 32 + t];
        sidx[t] = ix;
        out[ZQ_ELEMS + 1 + b * HW + h * 32 + t] = (float)ix;
    }
    __syncthreads();
    {
        const int wr = t >> 3;
        const int c0 = (t & 7) * 32;
        const float* er = emb + (size_t)sidx[wr] * DDIM + c0;
        for (int c = 0; c < 32; c += 4) {
            float4 v = *(const float4*)(er + c);
            Ts[wr][c0 + c + 0] = v.x;
            Ts[wr][c0 + c + 1] = v.y;
            Ts[wr][c0 + c + 2] = v.z;
            Ts[wr][c0 + c + 3] = v.w;
        }
    }
    __syncthreads();

    float ds = 0.f;
    const int w4  = (t & 7) * 4;
    const int c00 = t >> 3;
    const size_t basebh = (size_t)b * DDIM * HW + (size_t)h * 32;
#pragma unroll
    for (int it = 0; it < 8; it++) {
        int c = c00 + it * 32;
        float4 v;
        v.x = Ts[w4 + 0][c];
        v.y = Ts[w4 + 1][c];
        v.z = Ts[w4 + 2][c];
        v.w = Ts[w4 + 3][c];
        size_t gg = basebh + (size_t)c * HW + w4;
        float4 zv = *(const float4*)(z + gg);
        *(float4*)(out + gg) = v;
        float d0 = v.x - zv.x, d1 = v.y - zv.y;
        float d2 = v.z - zv.z, d3 = v.w - zv.w;
        ds += d0 * d0 + d1 * d1 + d2 * d2 + d3 * d3;
    }
#pragma unroll
    for (int o = 16; o; o >>= 1) ds += __shfl_xor_sync(0xffffffffu, ds, o);
    if ((t & 31) == 0) spart[t >> 5] = ds;
    __syncthreads();
    if (t == 0) {
        float s = 0.f;
#pragma unroll
        for (int i = 0; i < 8; i++) s += spart[i];
        atomicAdd(&g_diff, (double)s);
        __threadfence();
        int done = atomicAdd(&g_sdone, 1);
        if (done == BB * (HW / 32) - 1) {
            double dsum = *((volatile double*)&g_diff);
            out[ZQ_ELEMS] = (float)(0.25 * dsum / (double)ZQ_ELEMS);
        }
    }
}

extern "C" void kernel_launch(void* const* d_in, const int* in_sizes, int n_in,
                              void* d_out, int out_size) {
    const float* z   = (const float*)d_in[0];
    const float* emb = (const float*)d_in[1];
    float* out = (float*)d_out;

    cudaFuncSetAttribute(k_gemm,
                         cudaFuncAttributeMaxDynamicSharedMemorySize,
                         SMEM_ALLOC);

    k_prep<<<N_EMB / 8, 256>>>(emb);
    dim3 g(NQ / QT, SPLITS);
    k_gemm<<<g, 256, SMEM_ALLOC>>>(z);
    k_reduce<<<NQ / 256, 256>>>();
    k_refine<<<2048, 256>>>(z, emb);
    k_scatter<<<BB * (HW / 32), 256>>>(z, emb, out);
}

// round 16
// speedup vs baseline: 1.2677x; 1.0026x over previous
#include <cuda_runtime.h>
#include <cuda_fp16.h>
#include <cstdint>
#include <cfloat>

#define N_EMB   8192
#define DDIM    256
#define BB      32
#define HW      1024
#define NQ      32768
#define ZQ_ELEMS 8388608
#define SPLITS  8
#define KSPL    1024
#define QT      128
#define CCH     128
#define GCH     256
#define NST     32
#define TAU     0.16f

#define SM_A    0               // 128 q x 256 k halves, swizzled = 65536 B
#define SM_B    65536           // 2 stages x 16384 B
#define SM_EH   98304           // 1024 floats
#define SM_RED  106496          // rv1/ri1/rv2 3 x 2048 B
#define SMEM_ALLOC 112640

__device__ float  g_ehn[N_EMB];
__device__ __half g_eh[N_EMB * DDIM];
__device__ __half g_za[NQ * DDIM];     // pre-swizzled A images, 64KB per q-tile
__device__ float  g_p1v[SPLITS * NQ];
__device__ int    g_p1i[SPLITS * NQ];
__device__ float  g_p2v[SPLITS * NQ];
__device__ float  g_cmin[GCH * NQ];
__device__ float  g_b1[NQ];
__device__ int    g_idx[NQ];
__device__ int    g_flag[NQ];
__device__ int    g_nflag;
__device__ int    g_sdone;
__device__ int    g_qdone[NQ / QT];
__device__ double g_diff;

__device__ __forceinline__ uint32_t smem_u32(const void* p) {
    uint32_t a;
    asm("{ .reg .u64 t; cvta.to.shared.u64 t, %1; cvt.u32.u64 %0, t; }"
        : "=r"(a) : "l"(p));
    return a;
}
__device__ __forceinline__ void cp16(uint32_t s, const void* g) {
    asm volatile("cp.async.cg.shared.global [%0], [%1], 16;"
                 :: "r"(s), "l"(g) : "memory");
}
#define CP_COMMIT() asm volatile("cp.async.commit_group;" ::: "memory")
#define CP_WAIT0()  asm volatile("cp.async.wait_group 0;" ::: "memory")
#define BARX(id, n) asm volatile("bar.sync %0, %1;" :: "r"(id), "r"(n) : "memory")

#define LDMX4(r0, r1, r2, r3, addr) \
    asm volatile("ldmatrix.sync.aligned.m8n8.x4.shared.b16 {%0,%1,%2,%3},[%4];" \
        : "=r"(r0), "=r"(r1), "=r"(r2), "=r"(r3) : "r"(addr))
#define MMA_F16(d, a, b0, b1) \
    asm volatile("mma.sync.aligned.m16n8k16.row.col.f32.f16.f16.f32 " \
        "{%0,%1,%2,%3},{%4,%5,%6,%7},{%8,%9},{%0,%1,%2,%3};" \
        : "+f"((d)[0]), "+f"((d)[1]), "+f"((d)[2]), "+f"((d)[3]) \
        : "r"((a)[0]), "r"((a)[1]), "r"((a)[2]), "r"((a)[3]), "r"(b0), "r"(b1))

__global__ void k_prep(const float* __restrict__ emb) {
    if (blockIdx.x == 0 && threadIdx.x == 0) {
        g_diff = 0.0; g_nflag = 0; g_sdone = 0;
    }
    if (blockIdx.x == 0) g_qdone[threadIdx.x] = 0;
    int row  = blockIdx.x * 8 + (threadIdx.x >> 5);
    int lane = threadIdx.x & 31;
    const float4* e4 = (const float4*)(emb + (size_t)row * DDIM);
    __half2* eh2 = (__half2*)(g_eh + (size_t)row * DDIM);
    float s = 0.f;
    for (int i = lane; i < DDIM / 4; i += 32) {
        float4 v = e4[i];
        s += v.x * v.x + v.y * v.y + v.z * v.z + v.w * v.w;
        eh2[2 * i]     = __floats2half2_rn(v.x, v.y);
        eh2[2 * i + 1] = __floats2half2_rn(v.z, v.w);
    }
#pragma unroll
    for (int o = 16; o; o >>= 1) s += __shfl_xor_sync(0xffffffffu, s, o);
    if (lane == 0) g_ehn[row] = 0.5f * s;
}

// Build each q-tile's swizzled half A image once. grid 256, block 256.
__global__ void k_prepz(const float* __restrict__ z) {
    extern __shared__ char sm[];
    const int tid = threadIdx.x;
    const int qbase = blockIdx.x * QT;
    const int bb = qbase / HW, nb = qbase % HW;
    const float* zb = z + (size_t)bb * DDIM * HW + nb;
    for (int i = tid; i < QT * DDIM; i += 256) {
        int q = i & 127, k = i >> 7;
        __half hv = __float2half_rn(zb[(size_t)k * HW + q]);
        int kblk = k >> 3;
        uint32_t off = q * 512 + (((kblk & 24) | ((kblk ^ q) & 7)) << 4)
                     + (k & 7) * 2;
        *(__half*)(sm + off) = hv;
    }
    __syncthreads();
    const float4* src = (const float4*)sm;
    float4* dst = (float4*)(g_za + (size_t)blockIdx.x * (QT * DDIM));
#pragma unroll
    for (int it = 0; it < 16; it++) dst[it * 256 + tid] = src[it * 256 + tid];
}

// grid (NQ/QT=256, SPLITS=8), block 256 (8 warps: 2M x 4N), 2 CTAs/SM
__global__ void __launch_bounds__(256, 2)
k_gemm() {
    extern __shared__ char sm[];
    const uint32_t smA = smem_u32(sm);
    float* ehs = (float*)(sm + SM_EH);
    float* rv1 = (float*)(sm + SM_RED);
    int*   ri1 = (int*)(sm + SM_RED + 2048);
    float* rv2 = (float*)(sm + SM_RED + 4096);
    __shared__ int s_last;

    const int tid = threadIdx.x, wid = tid >> 5, lane = tid & 31;
    const int warpM = wid >> 2, warpN = wid & 3;
    const int g = lane >> 2, t = lane & 3;
    const int qbase = blockIdx.x * QT, sp = blockIdx.y;
    const int kbase = sp * KSPL;

    // A image: 16 coalesced cp.async per thread (pre-swizzled)
    {
        const float4* asrc =
            (const float4*)(g_za + (size_t)blockIdx.x * (QT * DDIM));
#pragma unroll
        for (int it = 0; it < 16; it++) {
            int i = it * 256 + tid;
            cp16(smA + i * 16, asrc + i);
        }
    }
    for (int i = tid; i < KSPL; i += 256) ehs[i] = g_ehn[kbase + i];

    auto prefetch = [&](int s) {
        int cc = s >> 2, kb = s & 3, buf = s & 1;
        const __half* src = g_eh + (size_t)(kbase + cc * CCH) * DDIM + kb * 64;
        uint32_t dst = smA + 65536 + buf * 16384;
#pragma unroll
        for (int it = 0; it < 4; it++) {
            int idx = it * 256 + tid;
            int code = idx >> 3, kblk = idx & 7;
            cp16(dst + code * 128 + (((kblk ^ code) & 7) << 4),
                 src + (size_t)code * DDIM + kblk * 8);
        }
    };

    float D[4][4][4];
    float bv1[4][2], bv2[4][2];
    int   bix[4][2];
#pragma unroll
    for (int a = 0; a < 4; a++)
#pragma unroll
        for (int h = 0; h < 2; h++) {
            bv1[a][h] = FLT_MAX; bv2[a][h] = FLT_MAX; bix[a][h] = 0;
        }

    prefetch(0);
    CP_COMMIT();
    const int r_ld  = (lane & 7) | (lane & 8);   // A frag row
    const int cbhi  = (lane >> 4) & 1;           // A col halfblock
    const int bquad = lane >> 3, brow8 = lane & 7;  // B LDMX4 lane map

    for (int s = 0; s < NST; s++) {
        CP_WAIT0();
        __syncthreads();          // buf s ready AND all warps done with s-1
        if (s + 1 < NST) { prefetch(s + 1); CP_COMMIT(); }
        if ((s & 3) == 0) {
#pragma unroll
            for (int mt = 0; mt < 4; mt++)
#pragma unroll
                for (int nt = 0; nt < 4; nt++)
#pragma unroll
                    for (int c = 0; c < 4; c++) D[mt][nt][c] = 0.f;
        }
        const uint32_t bst = smA + 65536 + (s & 1) * 16384;
#pragma unroll
        for (int ks = 0; ks < 4; ks++) {
            const int kk = (s & 3) * 4 + ks;
            const int cb = kk * 2 + cbhi;
            uint32_t a[4][4];
#pragma unroll
            for (int mt = 0; mt < 4; mt++) {
                int mrow = warpM * 64 + mt * 16 + r_ld;
                uint32_t ad = smA + mrow * 512
                            + (((cb & 24) | ((cb ^ mrow) & 7)) << 4);
                LDMX4(a[mt][0], a[mt][1], a[mt][2], a[mt][3], ad);
            }
#pragma unroll
            for (int np = 0; np < 2; np++) {
                int code = warpN * 32 + (2 * np + (bquad >> 1)) * 8 + brow8;
                int kb2  = ks * 2 + (bquad & 1);
                uint32_t bad = bst + code * 128 + (((kb2 ^ code) & 7) << 4);
                uint32_t b0, b1, b2, b3;
                LDMX4(b0, b1, b2, b3, bad);
#pragma unroll
                for (int mt = 0; mt < 4; mt++) {
                    MMA_F16(D[mt][2 * np],     a[mt], b0, b1);
                    MMA_F16(D[mt][2 * np + 1], a[mt], b2, b3);
                }
            }
        }
        if ((s & 3) == 3) {
            const int cc = s >> 2;
            float eh[4][2];
#pragma unroll
            for (int nt = 0; nt < 4; nt++) {
                int cl = cc * CCH + warpN * 32 + nt * 8 + 2 * t;
                eh[nt][0] = ehs[cl]; eh[nt][1] = ehs[cl + 1];
            }
#pragma unroll
            for (int mt = 0; mt < 4; mt++)
#pragma unroll
                for (int h = 0; h < 2; h++) {
                    float cm = FLT_MAX;
#pragma unroll
                    for (int nt = 0; nt < 4; nt++)
#pragma unroll
                        for (int c = 0; c < 2; c++) {
                            float v = eh[nt][c] - D[mt][nt][h * 2 + c];
                            int gi = kbase + cc * CCH + warpN * 32 + nt * 8
                                   + 2 * t + c;
                            cm = fminf(cm, v);
                            if (v < bv1[mt][h] ||
                                (v == bv1[mt][h] && gi < bix[mt][h])) {
                                bv2[mt][h] = bv1[mt][h];
                                bv1[mt][h] = v; bix[mt][h] = gi;
                            } else {
                                bv2[mt][h] = fminf(bv2[mt][h], v);
                            }
                        }
                    cm = fminf(cm, __shfl_xor_sync(0xffffffffu, cm, 1));
                    cm = fminf(cm, __shfl_xor_sync(0xffffffffu, cm, 2));
                    if (t == 0) {
                        int slice = sp * 32 + cc * 4 + warpN;
                        int row = warpM * 64 + mt * 16 + h * 8 + g;
                        g_cmin[(size_t)slice * NQ + qbase + row] = cm;
                    }
                }
        }
    }
    __syncthreads();

#pragma unroll
    for (int mt = 0; mt < 4; mt++)
#pragma unroll
        for (int h = 0; h < 2; h++) {
            float v1 = bv1[mt][h], v2 = bv2[mt][h];
            int i1 = bix[mt][h];
#pragma unroll
            for (int o = 1; o <= 2; o <<= 1) {
                float pv1 = __shfl_xor_sync(0xffffffffu, v1, o);
                float pv2 = __shfl_xor_sync(0xffffffffu, v2, o);
                int   pi1 = __shfl_xor_sync(0xffffffffu, i1, o);
                if (pv1 < v1 || (pv1 == v1 && pi1 < i1)) {
                    v2 = fminf(v1, pv2); v1 = pv1; i1 = pi1;
                } else {
                    v2 = fminf(pv1, v2);
                }
            }
            if (t == 0) {
                int row = warpM * 64 + mt * 16 + h * 8 + g;
                rv1[row * 4 + warpN] = v1;
                ri1[row * 4 + warpN] = i1;
                rv2[row * 4 + warpN] = v2;
            }
        }
    __syncthreads();
    if (tid < 128) {
        float v1 = rv1[tid * 4]; int i1 = ri1[tid * 4]; float v2 = rv2[tid * 4];
#pragma unroll
        for (int wn = 1; wn < 4; wn++) {
            float pv1 = rv1[tid * 4 + wn], pv2 = rv2[tid * 4 + wn];
            int   pi1 = ri1[tid * 4 + wn];
            if (pv1 < v1 || (pv1 == v1 && pi1 < i1)) {
                v2 = fminf(v1, pv2); v1 = pv1; i1 = pi1;
            } else {
                v2 = fminf(pv1, v2);
            }
        }
        g_p1v[sp * NQ + qbase + tid] = v1;
        g_p1i[sp * NQ + qbase + tid] = i1;
        g_p2v[sp * NQ + qbase + tid] = v2;
    }
    // fused split-reduce: last-arriving split CTA for this q-tile merges
    __syncthreads();
    if (tid == 0) {
        __threadfence();
        s_last = (atomicAdd(&g_qdone[blockIdx.x], 1) == SPLITS - 1);
    }
    __syncthreads();
    if (s_last && tid < 128) {
        __threadfence();
        const int q = qbase + tid;
        float b1 = FLT_MAX, b2 = FLT_MAX;
        int i1 = 0;
#pragma unroll
        for (int s = 0; s < SPLITS; s++) {
            float v1 = g_p1v[s * NQ + q];
            int   ii = g_p1i[s * NQ + q];
            float v2 = g_p2v[s * NQ + q];
            if (v1 < b1) { b2 = b1; b1 = v1; i1 = ii; }
            else if (v1 < b2) b2 = v1;
            if (v2 < b2) b2 = v2;
        }
        g_idx[q] = i1;
        g_b1[q]  = b1;
        if (b2 - b1 <= TAU) {
            int p = atomicAdd(&g_nflag, 1);
            g_flag[p] = q;
        }
    }
}

// Two independent 128-thread groups per block, each refining its own query.
__global__ void __launch_bounds__(256, 2)
k_refine(const float* __restrict__ z, const float* __restrict__ emb) {
    __shared__ float zs[2][DDIM];
    __shared__ short clist[2][GCH];
    __shared__ int   ncand[2];
    __shared__ float wv[2][4];
    __shared__ int   wi[2][4];
    const int tid  = threadIdx.x;
    const int gsel = tid >> 7;
    const int ltid = tid & 127;
    const int lwid = (tid >> 5) & 3;
    const int lane = tid & 31;
    const int grp8 = lane >> 3, gl = lane & 7;
    const int nf = g_nflag;
    if (nf == 0) return;
    const int bar = 1 + gsel;

    for (int base = blockIdx.x * 2; base < nf; base += gridDim.x * 2) {
        const int fi = base + gsel;
        const bool active = fi < nf;
        const int q = active ? g_flag[fi] : g_flag[0];
        if (ltid == 0) ncand[gsel] = 0;
        BARX(bar, 128);
        {
            const float* zq = z + ((size_t)(q >> 10) * DDIM) * HW + (q & (HW - 1));
            zs[gsel][ltid]       = zq[(size_t)ltid * HW];
            zs[gsel][ltid + 128] = zq[(size_t)(ltid + 128) * HW];
        }
        const float thr = g_b1[q] + TAU;
#pragma unroll
        for (int hh = 0; hh < 2; hh++) {
            int sl = ltid + hh * 128;
            if (g_cmin[(size_t)sl * NQ + q] <= thr) {
                int p = atomicAdd(&ncand[gsel], 1);
                clist[gsel][p] = (short)sl;
            }
        }
        BARX(bar, 128);
        float4 zr[8];
#pragma unroll
        for (int j = 0; j < 8; j++)
            zr[j] = *(const float4*)(&zs[gsel][gl * 32 + j * 4]);
        const int nc = ncand[gsel];
        float bv = FLT_MAX;
        int   bi = 0x7fffffff;
        for (int ci = 0; ci < nc; ci++) {
            const int cb = clist[gsel][ci] * 32 + lwid * 8 + grp8;
#pragma unroll
            for (int p2 = 0; p2 < 2; p2++) {
                const int code = cb + p2 * 4;
                const float4* er =
                    (const float4*)(emb + (size_t)code * DDIM + gl * 32);
                float s = 0.f;
#pragma unroll
                for (int j = 0; j < 8; j++) {
                    float4 e = er[j];
                    s += e.x * zr[j].x + e.y * zr[j].y
                       + e.z * zr[j].z + e.w * zr[j].w;
                }
                s += __shfl_xor_sync(0xffffffffu, s, 1);
                s += __shfl_xor_sync(0xffffffffu, s, 2);
                s += __shfl_xor_sync(0xffffffffu, s, 4);
                float v = g_ehn[code] - s;
                if (v < bv || (v == bv && code < bi)) { bv = v; bi = code; }
            }
        }
#pragma unroll
        for (int o = 8; o <= 16; o <<= 1) {
            float pv = __shfl_xor_sync(0xffffffffu, bv, o);
            int   pi = __shfl_xor_sync(0xffffffffu, bi, o);
            if (pv < bv || (pv == bv && pi < bi)) { bv = pv; bi = pi; }
        }
        if (lane == 0) { wv[gsel][lwid] = bv; wi[gsel][lwid] = bi; }
        BARX(bar, 128);
        if (ltid == 0 && active) {
            float fv = wv[gsel][0]; int fx = wi[gsel][0];
#pragma unroll
            for (int w2 = 1; w2 < 4; w2++)
                if (wv[gsel][w2] < fv ||
                    (wv[gsel][w2] == fv && wi[gsel][w2] < fx)) {
                    fv = wv[gsel][w2]; fx = wi[gsel][w2];
                }
            g_idx[q] = fx;
        }
        BARX(bar, 128);
    }
}

__global__ void k_scatter(const float* __restrict__ z,
                          const float* __restrict__ emb,
                          float* __restrict__ out) {
    __shared__ float Ts[32][257];
    __shared__ int   sidx[32];
    __shared__ float spart[8];
    const int bh = blockIdx.x;
    const int b  = bh >> 5;
    const int h  = bh & 31;
    const int t  = threadIdx.x;

    if (t < 32) {
        int ix = g_idx[b * HW + h * 32 + t];
        sidx[t] = ix;
        out[ZQ_ELEMS + 1 + b * HW + h * 32 + t] = (float)ix;
    }
    __syncthreads();
    {
        const int wr = t >> 3;
        const int c0 = (t & 7) * 32;
        const float* er = emb + (size_t)sidx[wr] * DDIM + c0;
        for (int c = 0; c < 32; c += 4) {
            float4 v = *(const float4*)(er + c);
            Ts[wr][c0 + c + 0] = v.x;
            Ts[wr][c0 + c + 1] = v.y;
            Ts[wr][c0 + c + 2] = v.z;
            Ts[wr][c0 + c + 3] = v.w;
        }
    }
    __syncthreads();

    float ds = 0.f;
    const int w4  = (t & 7) * 4;
    const int c00 = t >> 3;
    const size_t basebh = (size_t)b * DDIM * HW + (size_t)h * 32;
#pragma unroll
    for (int it = 0; it < 8; it++) {
        int c = c00 + it * 32;
        float4 v;
        v.x = Ts[w4 + 0][c];
        v.y = Ts[w4 + 1][c];
        v.z = Ts[w4 + 2][c];
        v.w = Ts[w4 + 3][c];
        size_t gg = basebh + (size_t)c * HW + w4;
        float4 zv = *(const float4*)(z + gg);
        *(float4*)(out + gg) = v;
        float d0 = v.x - zv.x, d1 = v.y - zv.y;
        float d2 = v.z - zv.z, d3 = v.w - zv.w;
        ds += d0 * d0 + d1 * d1 + d2 * d2 + d3 * d3;
    }
#pragma unroll
    for (int o = 16; o; o >>= 1) ds += __shfl_xor_sync(0xffffffffu, ds, o);
    if ((t & 31) == 0) spart[t >> 5] = ds;
    __syncthreads();
    if (t == 0) {
        float s = 0.f;
#pragma unroll
        for (int i = 0; i < 8; i++) s += spart[i];
        atomicAdd(&g_diff, (double)s);
        __threadfence();
        int done = atomicAdd(&g_sdone, 1);
        if (done == BB * (HW / 32) - 1) {
            double dsum = *((volatile double*)&g_diff);
            out[ZQ_ELEMS] = (float)(0.25 * dsum / (double)ZQ_ELEMS);
        }
    }
}

extern "C" void kernel_launch(void* const* d_in, const int* in_sizes, int n_in,
                              void* d_out, int out_size) {
    const float* z   = (const float*)d_in[0];
    const float* emb = (const float*)d_in[1];
    float* out = (float*)d_out;

    cudaFuncSetAttribute(k_gemm,
                         cudaFuncAttributeMaxDynamicSharedMemorySize,
                         SMEM_ALLOC);
    cudaFuncSetAttribute(k_prepz,
                         cudaFuncAttributeMaxDynamicSharedMemorySize,
                         65536);

    k_prep<<<N_EMB / 8, 256>>>(emb);
    k_prepz<<<NQ / QT, 256, 65536>>>(z);
    dim3 g(NQ / QT, SPLITS);
    k_gemm<<<g, 256, SMEM_ALLOC>>>();
    k_refine<<<2048, 256>>>(z, emb);
    k_scatter<<<BB * (HW / 32), 256>>>(z, emb, out);
}

// round 17
// speedup vs baseline: 1.3364x; 1.0542x over previous
#include <cuda_runtime.h>
#include <cuda_fp16.h>
#include <cstdint>
#include <cfloat>

#define N_EMB   8192
#define DDIM    256
#define BB      32
#define HW      1024
#define NQ      32768
#define ZQ_ELEMS 8388608
#define SPLITS  8
#define KSPL    1024
#define QT      128
#define CCH     128
#define GCH     256
#define NST     32
#define TAU     0.16f

#define SM_A    0               // 128 q x 256 k halves, swizzled = 65536 B
#define SM_B    65536           // 2 stages x 16384 B
#define SM_EH   98304           // 1024 floats
#define SM_RED  106496          // rv1/ri1/rv2 3 x 2048 B
#define SMEM_ALLOC 112640

__device__ float  g_ehn[N_EMB];
__device__ __half g_eh[N_EMB * DDIM];
__device__ __half g_za[NQ * DDIM];
__device__ float  g_p1v[SPLITS * NQ];
__device__ int    g_p1i[SPLITS * NQ];
__device__ float  g_p2v[SPLITS * NQ];
__device__ float  g_cmin[GCH * NQ];
__device__ float  g_b1[NQ];
__device__ int    g_idx[NQ];
__device__ int    g_flag[NQ];
__device__ int    g_nflag;
__device__ int    g_sdone;
__device__ int    g_qdone[NQ / QT];
__device__ double g_diff;

__device__ __forceinline__ uint32_t smem_u32(const void* p) {
    uint32_t a;
    asm("{ .reg .u64 t; cvta.to.shared.u64 t, %1; cvt.u32.u64 %0, t; }"
        : "=r"(a) : "l"(p));
    return a;
}
__device__ __forceinline__ void cp16(uint32_t s, const void* g) {
    asm volatile("cp.async.cg.shared.global [%0], [%1], 16;"
                 :: "r"(s), "l"(g) : "memory");
}
#define CP_COMMIT() asm volatile("cp.async.commit_group;" ::: "memory")
#define CP_WAIT0()  asm volatile("cp.async.wait_group 0;" ::: "memory")
#define BARX(id, n) asm volatile("bar.sync %0, %1;" :: "r"(id), "r"(n) : "memory")

#define LDMX4(r0, r1, r2, r3, addr) \
    asm volatile("ldmatrix.sync.aligned.m8n8.x4.shared.b16 {%0,%1,%2,%3},[%4];" \
        : "=r"(r0), "=r"(r1), "=r"(r2), "=r"(r3) : "r"(addr))
#define MMA_F16(d, a, b0, b1) \
    asm volatile("mma.sync.aligned.m16n8k16.row.col.f32.f16.f16.f32 " \
        "{%0,%1,%2,%3},{%4,%5,%6,%7},{%8,%9},{%0,%1,%2,%3};" \
        : "+f"((d)[0]), "+f"((d)[1]), "+f"((d)[2]), "+f"((d)[3]) \
        : "r"((a)[0]), "r"((a)[1]), "r"((a)[2]), "r"((a)[3]), "r"(b0), "r"(b1))

// Merged prep: blocks [0,1024) convert emb + norms; [1024,1280) build A images.
__global__ void k_prep(const float* __restrict__ emb, const float* __restrict__ z) {
    extern __shared__ char sm[];
    const int tid = threadIdx.x;
    if (blockIdx.x < 1024) {
        if (blockIdx.x == 0 && tid == 0) {
            g_diff = 0.0; g_nflag = 0; g_sdone = 0;
        }
        if (blockIdx.x == 0) g_qdone[tid] = 0;
        int row  = blockIdx.x * 8 + (tid >> 5);
        int lane = tid & 31;
        const float4* e4 = (const float4*)(emb + (size_t)row * DDIM);
        __half2* eh2 = (__half2*)(g_eh + (size_t)row * DDIM);
        float s = 0.f;
        for (int i = lane; i < DDIM / 4; i += 32) {
            float4 v = e4[i];
            s += v.x * v.x + v.y * v.y + v.z * v.z + v.w * v.w;
            eh2[2 * i]     = __floats2half2_rn(v.x, v.y);
            eh2[2 * i + 1] = __floats2half2_rn(v.z, v.w);
        }
#pragma unroll
        for (int o = 16; o; o >>= 1) s += __shfl_xor_sync(0xffffffffu, s, o);
        if (lane == 0) g_ehn[row] = 0.5f * s;
    } else {
        const int qt = blockIdx.x - 1024;
        const int qbase = qt * QT;
        const int bb = qbase / HW, nb = qbase % HW;
        const float* zb = z + (size_t)bb * DDIM * HW + nb;
        for (int i = tid; i < QT * DDIM; i += 256) {
            int q = i & 127, k = i >> 7;
            __half hv = __float2half_rn(zb[(size_t)k * HW + q]);
            int kblk = k >> 3;
            uint32_t off = q * 512 + (((kblk & 24) | ((kblk ^ q) & 7)) << 4)
                         + (k & 7) * 2;
            *(__half*)(sm + off) = hv;
        }
        __syncthreads();
        const float4* src = (const float4*)sm;
        float4* dst = (float4*)(g_za + (size_t)qt * (QT * DDIM));
#pragma unroll
        for (int it = 0; it < 16; it++)
            dst[it * 256 + tid] = src[it * 256 + tid];
    }
}

// grid (NQ/QT=256, SPLITS=8), block 256 (8 warps: 2M x 4N), 2 CTAs/SM
__global__ void __launch_bounds__(256, 2)
k_gemm() {
    extern __shared__ char sm[];
    const uint32_t smA = smem_u32(sm);
    float* ehs = (float*)(sm + SM_EH);
    float* rv1 = (float*)(sm + SM_RED);
    int*   ri1 = (int*)(sm + SM_RED + 2048);
    float* rv2 = (float*)(sm + SM_RED + 4096);
    __shared__ int s_last;

    const int tid = threadIdx.x, wid = tid >> 5, lane = tid & 31;
    const int warpM = wid >> 2, warpN = wid & 3;
    const int g = lane >> 2, t = lane & 3;
    const int qbase = blockIdx.x * QT, sp = blockIdx.y;
    const int kbase = sp * KSPL;

    {
        const float4* asrc =
            (const float4*)(g_za + (size_t)blockIdx.x * (QT * DDIM));
#pragma unroll
        for (int it = 0; it < 16; it++) {
            int i = it * 256 + tid;
            cp16(smA + i * 16, asrc + i);
        }
    }
    for (int i = tid; i < KSPL; i += 256) ehs[i] = g_ehn[kbase + i];

    auto prefetch = [&](int s) {
        int cc = s >> 2, kb = s & 3, buf = s & 1;
        const __half* src = g_eh + (size_t)(kbase + cc * CCH) * DDIM + kb * 64;
        uint32_t dst = smA + 65536 + buf * 16384;
#pragma unroll
        for (int it = 0; it < 4; it++) {
            int idx = it * 256 + tid;
            int code = idx >> 3, kblk = idx & 7;
            cp16(dst + code * 128 + (((kblk ^ code) & 7) << 4),
                 src + (size_t)code * DDIM + kblk * 8);
        }
    };

    float D[4][4][4];
    float bv1[4][2], bv2[4][2];
    int   bix[4][2];
#pragma unroll
    for (int a = 0; a < 4; a++)
#pragma unroll
        for (int h = 0; h < 2; h++) {
            bv1[a][h] = FLT_MAX; bv2[a][h] = FLT_MAX; bix[a][h] = 0;
        }

    prefetch(0);
    CP_COMMIT();
    const int r_ld  = (lane & 7) | (lane & 8);
    const int cbhi  = (lane >> 4) & 1;
    const int bquad = lane >> 3, brow8 = lane & 7;

    for (int s = 0; s < NST; s++) {
        CP_WAIT0();
        __syncthreads();
        if (s + 1 < NST) { prefetch(s + 1); CP_COMMIT(); }
        if ((s & 3) == 0) {
#pragma unroll
            for (int mt = 0; mt < 4; mt++)
#pragma unroll
                for (int nt = 0; nt < 4; nt++)
#pragma unroll
                    for (int c = 0; c < 4; c++) D[mt][nt][c] = 0.f;
        }
        const uint32_t bst = smA + 65536 + (s & 1) * 16384;
#pragma unroll
        for (int ks = 0; ks < 4; ks++) {
            const int kk = (s & 3) * 4 + ks;
            const int cb = kk * 2 + cbhi;
            uint32_t a[4][4];
#pragma unroll
            for (int mt = 0; mt < 4; mt++) {
                int mrow = warpM * 64 + mt * 16 + r_ld;
                uint32_t ad = smA + mrow * 512
                            + (((cb & 24) | ((cb ^ mrow) & 7)) << 4);
                LDMX4(a[mt][0], a[mt][1], a[mt][2], a[mt][3], ad);
            }
#pragma unroll
            for (int np = 0; np < 2; np++) {
                int code = warpN * 32 + (2 * np + (bquad >> 1)) * 8 + brow8;
                int kb2  = ks * 2 + (bquad & 1);
                uint32_t bad = bst + code * 128 + (((kb2 ^ code) & 7) << 4);
                uint32_t b0, b1, b2, b3;
                LDMX4(b0, b1, b2, b3, bad);
#pragma unroll
                for (int mt = 0; mt < 4; mt++) {
                    MMA_F16(D[mt][2 * np],     a[mt], b0, b1);
                    MMA_F16(D[mt][2 * np + 1], a[mt], b2, b3);
                }
            }
        }
        if ((s & 3) == 3) {
            const int cc = s >> 2;
            float eh[4][2];
#pragma unroll
            for (int nt = 0; nt < 4; nt++) {
                int cl = cc * CCH + warpN * 32 + nt * 8 + 2 * t;
                eh[nt][0] = ehs[cl]; eh[nt][1] = ehs[cl + 1];
            }
#pragma unroll
            for (int mt = 0; mt < 4; mt++)
#pragma unroll
                for (int h = 0; h < 2; h++) {
                    float cm = FLT_MAX;
#pragma unroll
                    for (int nt = 0; nt < 4; nt++)
#pragma unroll
                        for (int c = 0; c < 2; c++) {
                            float v = eh[nt][c] - D[mt][nt][h * 2 + c];
                            int gi = kbase + cc * CCH + warpN * 32 + nt * 8
                                   + 2 * t + c;
                            cm = fminf(cm, v);
                            // ties -> b1==b2 -> flagged -> refine decides
                            if (v < bv1[mt][h]) {
                                bv2[mt][h] = bv1[mt][h];
                                bv1[mt][h] = v; bix[mt][h] = gi;
                            } else {
                                bv2[mt][h] = fminf(bv2[mt][h], v);
                            }
                        }
                    cm = fminf(cm, __shfl_xor_sync(0xffffffffu, cm, 1));
                    cm = fminf(cm, __shfl_xor_sync(0xffffffffu, cm, 2));
                    if (t == 0) {
                        int slice = sp * 32 + cc * 4 + warpN;
                        int row = warpM * 64 + mt * 16 + h * 8 + g;
                        g_cmin[(size_t)slice * NQ + qbase + row] = cm;
                    }
                }
        }
    }
    __syncthreads();

#pragma unroll
    for (int mt = 0; mt < 4; mt++)
#pragma unroll
        for (int h = 0; h < 2; h++) {
            float v1 = bv1[mt][h], v2 = bv2[mt][h];
            int i1 = bix[mt][h];
#pragma unroll
            for (int o = 1; o <= 2; o <<= 1) {
                float pv1 = __shfl_xor_sync(0xffffffffu, v1, o);
                float pv2 = __shfl_xor_sync(0xffffffffu, v2, o);
                int   pi1 = __shfl_xor_sync(0xffffffffu, i1, o);
                if (pv1 < v1) {
                    v2 = fminf(v1, pv2); v1 = pv1; i1 = pi1;
                } else {
                    v2 = fminf(pv1, v2);
                }
            }
            if (t == 0) {
                int row = warpM * 64 + mt * 16 + h * 8 + g;
                rv1[row * 4 + warpN] = v1;
                ri1[row * 4 + warpN] = i1;
                rv2[row * 4 + warpN] = v2;
            }
        }
    __syncthreads();
    if (tid < 128) {
        float v1 = rv1[tid * 4]; int i1 = ri1[tid * 4]; float v2 = rv2[tid * 4];
#pragma unroll
        for (int wn = 1; wn < 4; wn++) {
            float pv1 = rv1[tid * 4 + wn], pv2 = rv2[tid * 4 + wn];
            int   pi1 = ri1[tid * 4 + wn];
            if (pv1 < v1) {
                v2 = fminf(v1, pv2); v1 = pv1; i1 = pi1;
            } else {
                v2 = fminf(pv1, v2);
            }
        }
        g_p1v[sp * NQ + qbase + tid] = v1;
        g_p1i[sp * NQ + qbase + tid] = i1;
        g_p2v[sp * NQ + qbase + tid] = v2;
    }
    __syncthreads();
    if (tid == 0) {
        __threadfence();
        s_last = (atomicAdd(&g_qdone[blockIdx.x], 1) == SPLITS - 1);
    }
    __syncthreads();
    if (s_last && tid < 128) {
        __threadfence();
        const int q = qbase + tid;
        float b1 = FLT_MAX, b2 = FLT_MAX;
        int i1 = 0;
#pragma unroll
        for (int s = 0; s < SPLITS; s++) {
            float v1 = g_p1v[s * NQ + q];
            int   ii = g_p1i[s * NQ + q];
            float v2 = g_p2v[s * NQ + q];
            if (v1 < b1) { b2 = b1; b1 = v1; i1 = ii; }
            else if (v1 < b2) b2 = v1;
            if (v2 < b2) b2 = v2;
        }
        g_idx[q] = i1;
        g_b1[q]  = b1;
        if (b2 - b1 <= TAU) {
            int p = atomicAdd(&g_nflag, 1);
            g_flag[p] = q;
        }
    }
}

// Two independent 128-thread groups per block, each refining its own query.
__global__ void __launch_bounds__(256, 2)
k_refine(const float* __restrict__ z, const float* __restrict__ emb) {
    __shared__ float zs[2][DDIM];
    __shared__ short clist[2][GCH];
    __shared__ int   ncand[2];
    __shared__ float wv[2][4];
    __shared__ int   wi[2][4];
    const int tid  = threadIdx.x;
    const int gsel = tid >> 7;
    const int ltid = tid & 127;
    const int lwid = (tid >> 5) & 3;
    const int lane = tid & 31;
    const int grp8 = lane >> 3, gl = lane & 7;
    const int nf = g_nflag;
    if (nf == 0) return;
    const int bar = 1 + gsel;

    for (int base = blockIdx.x * 2; base < nf; base += gridDim.x * 2) {
        const int fi = base + gsel;
        const bool active = fi < nf;
        const int q = active ? g_flag[fi] : g_flag[0];
        if (ltid == 0) ncand[gsel] = 0;
        BARX(bar, 128);
        {
            const float* zq = z + ((size_t)(q >> 10) * DDIM) * HW + (q & (HW - 1));
            zs[gsel][ltid]       = zq[(size_t)ltid * HW];
            zs[gsel][ltid + 128] = zq[(size_t)(ltid + 128) * HW];
        }
        const float thr = g_b1[q] + TAU;
#pragma unroll
        for (int hh = 0; hh < 2; hh++) {
            int sl = ltid + hh * 128;
            if (g_cmin[(size_t)sl * NQ + q] <= thr) {
                int p = atomicAdd(&ncand[gsel], 1);
                clist[gsel][p] = (short)sl;
            }
        }
        BARX(bar, 128);
        float4 zr[8];
#pragma unroll
        for (int j = 0; j < 8; j++)
            zr[j] = *(const float4*)(&zs[gsel][gl * 32 + j * 4]);
        const int nc = ncand[gsel];
        float bv = FLT_MAX;
        int   bi = 0x7fffffff;
        for (int ci = 0; ci < nc; ci++) {
            const int cb = clist[gsel][ci] * 32 + lwid * 8 + grp8;
#pragma unroll
            for (int p2 = 0; p2 < 2; p2++) {
                const int code = cb + p2 * 4;
                const float4* er =
                    (const float4*)(emb + (size_t)code * DDIM + gl * 32);
                float s = 0.f;
#pragma unroll
                for (int j = 0; j < 8; j++) {
                    float4 e = er[j];
                    s += e.x * zr[j].x + e.y * zr[j].y
                       + e.z * zr[j].z + e.w * zr[j].w;
                }
                s += __shfl_xor_sync(0xffffffffu, s, 1);
                s += __shfl_xor_sync(0xffffffffu, s, 2);
                s += __shfl_xor_sync(0xffffffffu, s, 4);
                float v = g_ehn[code] - s;
                if (v < bv || (v == bv && code < bi)) { bv = v; bi = code; }
            }
        }
#pragma unroll
        for (int o = 8; o <= 16; o <<= 1) {
            float pv = __shfl_xor_sync(0xffffffffu, bv, o);
            int   pi = __shfl_xor_sync(0xffffffffu, bi, o);
            if (pv < bv || (pv == bv && pi < bi)) { bv = pv; bi = pi; }
        }
        if (lane == 0) { wv[gsel][lwid] = bv; wi[gsel][lwid] = bi; }
        BARX(bar, 128);
        if (ltid == 0 && active) {
            float fv = wv[gsel][0]; int fx = wi[gsel][0];
#pragma unroll
            for (int w2 = 1; w2 < 4; w2++)
                if (wv[gsel][w2] < fv ||
                    (wv[gsel][w2] == fv && wi[gsel][w2] < fx)) {
                    fv = wv[gsel][w2]; fx = wi[gsel][w2];
                }
            g_idx[q] = fx;
        }
        BARX(bar, 128);
    }
}

__global__ void k_scatter(const float* __restrict__ z,
                          const float* __restrict__ emb,
                          float* __restrict__ out) {
    __shared__ float Ts[32][257];
    __shared__ int   sidx[32];
    __shared__ float spart[8];
    const int bh = blockIdx.x;
    const int b  = bh >> 5;
    const int h  = bh & 31;
    const int t  = threadIdx.x;

    if (t < 32) {
        int ix = g_idx[b * HW + h * 32 + t];
        sidx[t] = ix;
        out[ZQ_ELEMS + 1 + b * HW + h * 32 + t] = (float)ix;
    }
    __syncthreads();
    {
        const int wr = t >> 3;
        const int c0 = (t & 7) * 32;
        const float* er = emb + (size_t)sidx[wr] * DDIM + c0;
        for (int c = 0; c < 32; c += 4) {
            float4 v = *(const float4*)(er + c);
            Ts[wr][c0 + c + 0] = v.x;
            Ts[wr][c0 + c + 1] = v.y;
            Ts[wr][c0 + c + 2] = v.z;
            Ts[wr][c0 + c + 3] = v.w;
        }
    }
    __syncthreads();

    float ds = 0.f;
    const int w4  = (t & 7) * 4;
    const int c00 = t >> 3;
    const size_t basebh = (size_t)b * DDIM * HW + (size_t)h * 32;
#pragma unroll
    for (int it = 0; it < 8; it++) {
        int c = c00 + it * 32;
        float4 v;
        v.x = Ts[w4 + 0][c];
        v.y = Ts[w4 + 1][c];
        v.z = Ts[w4 + 2][c];
        v.w = Ts[w4 + 3][c];
        size_t gg = basebh + (size_t)c * HW + w4;
        float4 zv = *(const float4*)(z + gg);
        *(float4*)(out + gg) = v;
        float d0 = v.x - zv.x, d1 = v.y - zv.y;
        float d2 = v.z - zv.z, d3 = v.w - zv.w;
        ds += d0 * d0 + d1 * d1 + d2 * d2 + d3 * d3;
    }
#pragma unroll
    for (int o = 16; o; o >>= 1) ds += __shfl_xor_sync(0xffffffffu, ds, o);
    if ((t & 31) == 0) spart[t >> 5] = ds;
    __syncthreads();
    if (t == 0) {
        float s = 0.f;
#pragma unroll
        for (int i = 0; i < 8; i++) s += spart[i];
        atomicAdd(&g_diff, (double)s);
        __threadfence();
        int done = atomicAdd(&g_sdone, 1);
        if (done == BB * (HW / 32) - 1) {
            double dsum = *((volatile double*)&g_diff);
            out[ZQ_ELEMS] = (float)(0.25 * dsum / (double)ZQ_ELEMS);
        }
    }
}

extern "C" void kernel_launch(void* const* d_in, const int* in_sizes, int n_in,
                              void* d_out, int out_size) {
    const float* z   = (const float*)d_in[0];
    const float* emb = (const float*)d_in[1];
    float* out = (float*)d_out;

    cudaFuncSetAttribute(k_gemm,
                         cudaFuncAttributeMaxDynamicSharedMemorySize,
                         SMEM_ALLOC);
    cudaFuncSetAttribute(k_prep,
                         cudaFuncAttributeMaxDynamicSharedMemorySize,
                         65536);

    k_prep<<<1280, 256, 65536>>>(emb, z);
    dim3 g(NQ / QT, SPLITS);
    k_gemm<<<g, 256, SMEM_ALLOC>>>();
    k_refine<<<2048, 256>>>(z, emb);
    k_scatter<<<BB * (HW / 32), 256>>>(z, emb, out);
}